// round 1
// baseline (speedup 1.0000x reference)
#include <cuda_runtime.h>
#include <cuda_bf16.h>
#include <math.h>

// Problem constants (fixed by the reference)
#define BATCH   2
#define SEQ     2048
#define DMODEL  1024
#define NHEAD   16
#define HDIM    64
#define BH      (BATCH*NHEAD)      // 32
#define ROWS    (BATCH*SEQ)        // 4096
#define U_TOP   38                 // int(5 * ln(2048)) = 38
#define CAP     128                // compacted index list capacity per row

// ---------------- scratch (allocation-free rule: __device__ globals) --------
__device__ float g_Q[ROWS * DMODEL];
__device__ float g_Kp[ROWS * DMODEL];
__device__ float g_Vp[ROWS * DMODEL];
__device__ float g_ctx[ROWS * DMODEL];

// ---------------- SGEMM:  C[m][n] = sum_k A[m][k] * B[n][k] + bias[n] -------
// A: [M,K] row-major, B: [N,K] row-major (i.e. x @ W^T), M,N multiples of 128,
// K multiple of 16.
#define BM 128
#define BN 128
#define BK 16

__global__ __launch_bounds__(256)
void sgemm_nt_bias(const float* __restrict__ A, const float* __restrict__ Bw,
                   const float* __restrict__ bias, float* __restrict__ C,
                   int M, int N, int K)
{
    __shared__ float As[BK][BM];
    __shared__ float Bs[BK][BN];

    const int tid = threadIdx.x;
    const int m0 = blockIdx.y * BM;
    const int n0 = blockIdx.x * BN;
    const int tx = tid & 15;   // n-dir
    const int ty = tid >> 4;   // m-dir

    float acc[8][8];
#pragma unroll
    for (int i = 0; i < 8; i++)
#pragma unroll
        for (int j = 0; j < 8; j++) acc[i][j] = 0.f;

    for (int k0 = 0; k0 < K; k0 += BK) {
#pragma unroll
        for (int i = 0; i < 2; i++) {
            int fidx = tid + i * 256;       // 0..511
            int row  = fidx >> 2;           // 0..127
            int kq   = fidx & 3;            // 0..3  (4 float4 per row)
            float4 va = *(const float4*)(A  + (size_t)(m0 + row) * K + k0 + kq * 4);
            As[kq*4+0][row] = va.x; As[kq*4+1][row] = va.y;
            As[kq*4+2][row] = va.z; As[kq*4+3][row] = va.w;
            float4 vb = *(const float4*)(Bw + (size_t)(n0 + row) * K + k0 + kq * 4);
            Bs[kq*4+0][row] = vb.x; Bs[kq*4+1][row] = vb.y;
            Bs[kq*4+2][row] = vb.z; Bs[kq*4+3][row] = vb.w;
        }
        __syncthreads();
#pragma unroll
        for (int kk = 0; kk < BK; kk++) {
            float a[8], b[8];
            *(float4*)&a[0] = *(float4*)&As[kk][ty * 8];
            *(float4*)&a[4] = *(float4*)&As[kk][ty * 8 + 4];
            *(float4*)&b[0] = *(float4*)&Bs[kk][tx * 8];
            *(float4*)&b[4] = *(float4*)&Bs[kk][tx * 8 + 4];
#pragma unroll
            for (int i = 0; i < 8; i++)
#pragma unroll
                for (int j = 0; j < 8; j++)
                    acc[i][j] += a[i] * b[j];
        }
        __syncthreads();
    }

    float bc[8];
#pragma unroll
    for (int j = 0; j < 8; j++) bc[j] = bias[n0 + tx * 8 + j];

#pragma unroll
    for (int i = 0; i < 8; i++) {
        float* crow = C + (size_t)(m0 + ty * 8 + i) * N + n0 + tx * 8;
        float4 o0 = make_float4(acc[i][0] + bc[0], acc[i][1] + bc[1],
                                acc[i][2] + bc[2], acc[i][3] + bc[3]);
        float4 o1 = make_float4(acc[i][4] + bc[4], acc[i][5] + bc[5],
                                acc[i][6] + bc[6], acc[i][7] + bc[7]);
        *(float4*)(crow + 0) = o0;
        *(float4*)(crow + 4) = o1;
    }
}

// ---------------- fused ProbSparse attention --------------------------------
// One block per (bh, 16-query tile). Phase 1: S[16][2048] = QK^T/8 into smem.
// Phase 2 (per warp, 2 rows each): exact radix-select of the U-th largest
// score, masked softmax, sparse gather AV into ctx (layout [B*L, H*D]).

#define TQ 16
#define KT 256

__device__ __forceinline__ unsigned fkey(float x) {
    unsigned u = __float_as_uint(x);
    return (u & 0x80000000u) ? ~u : (u | 0x80000000u);   // order-preserving map
}

// smem layout (floats): S[TQ*SEQ] | Qs[TQ*64] | Ks[KT*64] | hist[8*256 u32]
//                       | idxl[TQ*CAP i32] | wl[TQ*CAP f32]
#define ATTN_SMEM_BYTES ((TQ*SEQ + TQ*64 + KT*64) * 4 + 8*256*4 + TQ*CAP*4 + TQ*CAP*4)

__global__ __launch_bounds__(256)
void attn_kernel(const float* __restrict__ Q, const float* __restrict__ K,
                 const float* __restrict__ V, float* __restrict__ ctx)
{
    extern __shared__ char smraw[];
    float*    S    = (float*)smraw;                 // TQ * SEQ
    float*    Qs   = S  + TQ * SEQ;                 // TQ * 64
    float*    Ks   = Qs + TQ * 64;                  // KT * 64 (xor-swizzled f4)
    unsigned* hist = (unsigned*)(Ks + KT * 64);     // 8 warps * 256 bins
    int*      idxl = (int*)(hist + 8 * 256);        // TQ * CAP
    float*    wl   = (float*)(idxl + TQ * CAP);     // TQ * CAP

    const int tid = threadIdx.x;
    const int qt  = blockIdx.x;          // 0..127
    const int bh  = blockIdx.y;          // 0..31
    const int b   = bh >> 4, h = bh & 15;
    const int q0  = qt * TQ;

    const float* Qbase = Q + ((size_t)b * SEQ + q0) * DMODEL + h * HDIM;
    const float* Kbase = K + ((size_t)b * SEQ) * DMODEL + h * HDIM;
    const float* Vbase = V + ((size_t)b * SEQ) * DMODEL + h * HDIM;

    // load Q tile (16 rows x 64)
    {
        int row = tid >> 4, c4 = tid & 15;
        *(float4*)(Qs + row * 64 + c4 * 4) =
            *(const float4*)(Qbase + (size_t)row * DMODEL + c4 * 4);
    }

    // ---- phase 1: scores ----
    const int kq = tid & 63;   // k-group (4 consecutive k)
    const int qg = tid >> 6;   // q-group (4 consecutive q)
    const int swz = kq & 15;

    for (int kt = 0; kt < SEQ / KT; kt++) {
        __syncthreads();   // Qs ready (iter 0) / Ks consumers done (iter >0)
#pragma unroll
        for (int i = 0; i < 16; i++) {
            int fidx = i * 256 + tid;          // 0..4095
            int row  = fidx >> 4;              // 0..255
            int d4   = fidx & 15;
            float4 v = *(const float4*)(Kbase + (size_t)(kt * KT + row) * DMODEL + d4 * 4);
            *(float4*)(Ks + row * 64 + ((d4 ^ ((row >> 2) & 15)) << 2)) = v;
        }
        __syncthreads();

        float acc[4][4];
#pragma unroll
        for (int j = 0; j < 4; j++)
#pragma unroll
            for (int i = 0; i < 4; i++) acc[j][i] = 0.f;

#pragma unroll
        for (int d4 = 0; d4 < 16; d4++) {
            float4 kv[4];
#pragma unroll
            for (int i = 0; i < 4; i++)
                kv[i] = *(float4*)(Ks + (kq * 4 + i) * 64 + ((d4 ^ swz) << 2));
#pragma unroll
            for (int j = 0; j < 4; j++) {
                float4 qv = *(float4*)(Qs + (qg * 4 + j) * 64 + (d4 << 2));
#pragma unroll
                for (int i = 0; i < 4; i++)
                    acc[j][i] += qv.x * kv[i].x + qv.y * kv[i].y +
                                 qv.z * kv[i].z + qv.w * kv[i].w;
            }
        }
#pragma unroll
        for (int j = 0; j < 4; j++) {
            float4 o = make_float4(acc[j][0] * 0.125f, acc[j][1] * 0.125f,
                                   acc[j][2] * 0.125f, acc[j][3] * 0.125f);
            *(float4*)(S + (size_t)(qg * 4 + j) * SEQ + kt * KT + kq * 4) = o;
        }
    }
    __syncthreads();

    // ---- phase 2: per-row top-U select + softmax + sparse AV ----
    const int lane = tid & 31, wid = tid >> 5;
    unsigned* myhist = hist + wid * 256;

    for (int rr = 0; rr < 2; rr++) {
        const int q = wid * 2 + rr;
        const float* Srow = S + (size_t)q * SEQ;

        // row max
        float m = -1e30f;
        for (int i = lane; i < SEQ; i += 32) m = fmaxf(m, Srow[i]);
#pragma unroll
        for (int off = 16; off; off >>= 1)
            m = fmaxf(m, __shfl_xor_sync(0xffffffffu, m, off));

        // exact radix select of the U_TOP-th largest key (MSB -> LSB, 8b digits)
        unsigned prefix = 0;
        int remaining = U_TOP;
        for (int pass = 0; pass < 4; pass++) {
            const int shift = 24 - pass * 8;
#pragma unroll
            for (int j = 0; j < 8; j++) myhist[lane * 8 + j] = 0;
            __syncwarp();
            for (int i = lane; i < SEQ; i += 32) {
                unsigned key = fkey(Srow[i]);
                bool ok = (pass == 0) || ((key >> (shift + 8)) == prefix);
                if (ok) atomicAdd(&myhist[(key >> shift) & 255], 1u);
            }
            __syncwarp();
            unsigned psum = 0;
#pragma unroll
            for (int j = 0; j < 8; j++) psum += myhist[lane * 8 + j];
            unsigned c = psum;                         // inclusive suffix sum
#pragma unroll
            for (int off = 1; off < 32; off <<= 1) {
                unsigned o = __shfl_down_sync(0xffffffffu, c, off);
                if (lane + off < 32) c += o;
            }
            unsigned mk = __ballot_sync(0xffffffffu, c >= (unsigned)remaining);
            int lsel = 31 - __clz(mk);                 // highest lane crossing
            int digit = 0, newrem = remaining;
            if (lane == lsel) {
                unsigned cum = c - psum;               // count strictly above my bins
                for (int j = 7; j >= 0; j--) {
                    unsigned hv = myhist[lsel * 8 + j];
                    cum += hv;
                    if (cum >= (unsigned)remaining) {
                        digit = lsel * 8 + j;
                        newrem = remaining - (int)(cum - hv);
                        break;
                    }
                }
            }
            digit  = __shfl_sync(0xffffffffu, digit, lsel);
            newrem = __shfl_sync(0xffffffffu, newrem, lsel);
            prefix = (prefix << 8) | (unsigned)digit;
            remaining = newrem;
            __syncwarp();
        }
        const unsigned kth = prefix;  // exact bit pattern of the U-th largest

        // deterministic warp compaction + exp-sum (keep s >= thresh)
        float lsum = 0.f;
        int cnt = 0;
        for (int base = 0; base < SEQ; base += 32) {
            int i = base + lane;
            float s = Srow[i];
            bool keep = fkey(s) >= kth;
            unsigned bm = __ballot_sync(0xffffffffu, keep);
            if (keep) {
                int pos = cnt + __popc(bm & ((1u << lane) - 1u));
                float w = expf(s - m);
                lsum += w;
                if (pos < CAP) { idxl[q * CAP + pos] = i; wl[q * CAP + pos] = w; }
            }
            cnt += __popc(bm);
        }
#pragma unroll
        for (int off = 16; off; off >>= 1)
            lsum += __shfl_xor_sync(0xffffffffu, lsum, off);
        const float scale = 1.f / lsum;

        // sparse AV gather (lane owns dims lane and lane+32)
        float c0 = 0.f, c1 = 0.f;
        if (cnt <= CAP) {
            for (int j = 0; j < cnt; j++) {
                int kkidx = idxl[q * CAP + j];
                float w = wl[q * CAP + j] * scale;
                const float* vr = Vbase + (size_t)kkidx * DMODEL;
                c0 += w * vr[lane];
                c1 += w * vr[lane + 32];
            }
        } else {  // pathological tie overflow: dense fallback (exact)
            for (int i = 0; i < SEQ; i++) {
                float s = Srow[i];
                if (fkey(s) >= kth) {
                    float w = expf(s - m) * scale;
                    const float* vr = Vbase + (size_t)i * DMODEL;
                    c0 += w * vr[lane];
                    c1 += w * vr[lane + 32];
                }
            }
        }
        float* orow = ctx + ((size_t)b * SEQ + q0 + q) * DMODEL + h * HDIM;
        orow[lane]      = c0;
        orow[lane + 32] = c1;
    }
}

// ---------------- launch ----------------------------------------------------
extern "C" void kernel_launch(void* const* d_in, const int* in_sizes, int n_in,
                              void* d_out, int out_size)
{
    const float* x  = (const float*)d_in[0];
    const float* Wq = (const float*)d_in[1];
    const float* bq = (const float*)d_in[2];
    const float* Wk = (const float*)d_in[3];
    const float* bk = (const float*)d_in[4];
    const float* Wv = (const float*)d_in[5];
    const float* bv = (const float*)d_in[6];
    const float* Wo = (const float*)d_in[7];
    const float* bo = (const float*)d_in[8];
    float* out = (float*)d_out;

    float *Q, *K, *V, *C;
    cudaGetSymbolAddress((void**)&Q, g_Q);
    cudaGetSymbolAddress((void**)&K, g_Kp);
    cudaGetSymbolAddress((void**)&V, g_Vp);
    cudaGetSymbolAddress((void**)&C, g_ctx);

    dim3 gG(DMODEL / BN, ROWS / BM);   // (8, 32)
    sgemm_nt_bias<<<gG, 256>>>(x, Wq, bq, Q, ROWS, DMODEL, DMODEL);
    sgemm_nt_bias<<<gG, 256>>>(x, Wk, bk, K, ROWS, DMODEL, DMODEL);
    sgemm_nt_bias<<<gG, 256>>>(x, Wv, bv, V, ROWS, DMODEL, DMODEL);

    cudaFuncSetAttribute(attn_kernel, cudaFuncAttributeMaxDynamicSharedMemorySize,
                         ATTN_SMEM_BYTES);
    attn_kernel<<<dim3(SEQ / TQ, BH), 256, ATTN_SMEM_BYTES>>>(Q, K, V, C);

    sgemm_nt_bias<<<gG, 256>>>(C, Wo, bo, out, ROWS, DMODEL, DMODEL);
}

// round 2
// speedup vs baseline: 1.0299x; 1.0299x over previous
#include <cuda_runtime.h>
#include <cuda_bf16.h>
#include <math.h>

// Problem constants (fixed by the reference)
#define BATCH   2
#define SEQ     2048
#define DMODEL  1024
#define NHEAD   16
#define HDIM    64
#define BH      (BATCH*NHEAD)      // 32
#define ROWS    (BATCH*SEQ)        // 4096
#define U_TOP   38                 // int(5 * ln(2048)) = 38
#define CAP     128                // compacted index list capacity per row

typedef unsigned long long ull;

// ---- packed f32x2 helpers (sm_100+: FFMA2 — 2x fp32 FMA per instruction) ---
__device__ __forceinline__ ull pk2(float x, float y) {
    ull r; asm("mov.b64 %0, {%1, %2};" : "=l"(r) : "f"(x), "f"(y)); return r;
}
__device__ __forceinline__ void ffma2(ull& d, ull a, ull b) {
    asm("fma.rn.f32x2 %0, %1, %2, %0;" : "+l"(d) : "l"(a), "l"(b));
}
__device__ __forceinline__ float2 up2(ull v) {
    float2 f; asm("mov.b64 {%0, %1}, %2;" : "=f"(f.x), "=f"(f.y) : "l"(v)); return f;
}
union f4u { float4 f; ull u[2]; };

// ---------------- scratch (allocation-free rule: __device__ globals) --------
__device__ float g_Q[ROWS * DMODEL];
__device__ float g_Kp[ROWS * DMODEL];
__device__ float g_Vp[ROWS * DMODEL];
__device__ float g_ctx[ROWS * DMODEL];

// ---------------- SGEMM:  C[m][n] = sum_k A[m][k] * B[n][k] + bias[n] -------
#define BM 128
#define BN 128
#define BK 16

__device__ __forceinline__
void gemm_body(const float* __restrict__ A, const float* __restrict__ Bw,
               const float* __restrict__ bias, float* __restrict__ C,
               int m0, int n0, int K, int N)
{
    __shared__ float As[BK][BM];
    __shared__ float Bs[BK][BN];

    const int tid = threadIdx.x;
    const int tx = tid & 15;   // n-dir
    const int ty = tid >> 4;   // m-dir

    ull acc2[8][4];            // 8 m-rows x 4 n-pairs (packed fp32x2)
#pragma unroll
    for (int i = 0; i < 8; i++)
#pragma unroll
        for (int j = 0; j < 4; j++) acc2[i][j] = 0ull;

    for (int k0 = 0; k0 < K; k0 += BK) {
#pragma unroll
        for (int i = 0; i < 2; i++) {
            int fidx = tid + i * 256;       // 0..511
            int row  = fidx >> 2;           // 0..127
            int kq   = fidx & 3;            // 0..3  (4 float4 per row)
            float4 va = *(const float4*)(A  + (size_t)(m0 + row) * K + k0 + kq * 4);
            As[kq*4+0][row] = va.x; As[kq*4+1][row] = va.y;
            As[kq*4+2][row] = va.z; As[kq*4+3][row] = va.w;
            float4 vb = *(const float4*)(Bw + (size_t)(n0 + row) * K + k0 + kq * 4);
            Bs[kq*4+0][row] = vb.x; Bs[kq*4+1][row] = vb.y;
            Bs[kq*4+2][row] = vb.z; Bs[kq*4+3][row] = vb.w;
        }
        __syncthreads();
#pragma unroll
        for (int kk = 0; kk < BK; kk++) {
            float a[8];
            *(float4*)&a[0] = *(float4*)&As[kk][ty * 8];
            *(float4*)&a[4] = *(float4*)&As[kk][ty * 8 + 4];
            f4u b0, b1;
            b0.f = *(float4*)&Bs[kk][tx * 8];
            b1.f = *(float4*)&Bs[kk][tx * 8 + 4];
            ull b2[4] = { b0.u[0], b0.u[1], b1.u[0], b1.u[1] };
#pragma unroll
            for (int i = 0; i < 8; i++) {
                ull ai = pk2(a[i], a[i]);
#pragma unroll
                for (int j = 0; j < 4; j++) ffma2(acc2[i][j], ai, b2[j]);
            }
        }
        __syncthreads();
    }

    float bc[8];
#pragma unroll
    for (int j = 0; j < 8; j++) bc[j] = bias[n0 + tx * 8 + j];

#pragma unroll
    for (int i = 0; i < 8; i++) {
        float* crow = C + (size_t)(m0 + ty * 8 + i) * N + n0 + tx * 8;
        float2 p0 = up2(acc2[i][0]), p1 = up2(acc2[i][1]);
        float2 p2 = up2(acc2[i][2]), p3 = up2(acc2[i][3]);
        float4 o0 = make_float4(p0.x + bc[0], p0.y + bc[1], p1.x + bc[2], p1.y + bc[3]);
        float4 o1 = make_float4(p2.x + bc[4], p2.y + bc[5], p3.x + bc[6], p3.y + bc[7]);
        *(float4*)(crow + 0) = o0;
        *(float4*)(crow + 4) = o1;
    }
}

__global__ __launch_bounds__(256)
void sgemm_nt_bias(const float* __restrict__ A, const float* __restrict__ Bw,
                   const float* __restrict__ bias, float* __restrict__ C,
                   int M, int N, int K)
{
    gemm_body(A, Bw, bias, C, blockIdx.y * BM, blockIdx.x * BN, K, N);
}

// fused Q/K/V projection: 3 GEMMs in one grid (blockIdx.x selects matrix)
__global__ __launch_bounds__(256)
void qkv_gemm(const float* __restrict__ x,
              const float* __restrict__ Wq, const float* __restrict__ bq, float* __restrict__ Q,
              const float* __restrict__ Wk, const float* __restrict__ bk, float* __restrict__ K,
              const float* __restrict__ Wv, const float* __restrict__ bv, float* __restrict__ V)
{
    const int sel  = blockIdx.x >> 3;          // 0..2
    const int nblk = blockIdx.x & 7;
    const float* W = (sel == 0) ? Wq : (sel == 1) ? Wk : Wv;
    const float* b = (sel == 0) ? bq : (sel == 1) ? bk : bv;
    float*       C = (sel == 0) ? Q  : (sel == 1) ? K  : V;
    gemm_body(x, W, b, C, blockIdx.y * BM, nblk * BN, DMODEL, DMODEL);
}

// ---------------- fused ProbSparse attention --------------------------------
#define TQ 16
#define KT 256

__device__ __forceinline__ unsigned fkey(float x) {
    unsigned u = __float_as_uint(x);
    return (u & 0x80000000u) ? ~u : (u | 0x80000000u);   // order-preserving map
}

#define ATTN_SMEM_BYTES ((TQ*SEQ + TQ*64 + KT*64) * 4 + 8*256*4 + TQ*CAP*4 + TQ*CAP*4)

__global__ __launch_bounds__(256)
void attn_kernel(const float* __restrict__ Q, const float* __restrict__ K,
                 const float* __restrict__ V, float* __restrict__ ctx)
{
    extern __shared__ char smraw[];
    float*    S    = (float*)smraw;                 // TQ * SEQ
    float*    Qs   = S  + TQ * SEQ;                 // TQ * 64
    float*    Ks   = Qs + TQ * 64;                  // KT * 64 (xor-swizzled f4)
    unsigned* hist = (unsigned*)(Ks + KT * 64);     // 8 warps * 256 bins
    int*      idxl = (int*)(hist + 8 * 256);        // TQ * CAP
    float*    wl   = (float*)(idxl + TQ * CAP);     // TQ * CAP

    const int tid = threadIdx.x;
    const int qt  = blockIdx.x;          // 0..127
    const int bh  = blockIdx.y;          // 0..31
    const int b   = bh >> 4, h = bh & 15;
    const int q0  = qt * TQ;

    const float* Qbase = Q + ((size_t)b * SEQ + q0) * DMODEL + h * HDIM;
    const float* Kbase = K + ((size_t)b * SEQ) * DMODEL + h * HDIM;
    const float* Vbase = V + ((size_t)b * SEQ) * DMODEL + h * HDIM;

    // load Q tile (16 rows x 64)
    {
        int row = tid >> 4, c4 = tid & 15;
        *(float4*)(Qs + row * 64 + c4 * 4) =
            *(const float4*)(Qbase + (size_t)row * DMODEL + c4 * 4);
    }

    // ---- phase 1: scores (packed f32x2 along head dim) ----
    const int kq = tid & 63;   // k-group (4 consecutive k)
    const int qg = tid >> 6;   // q-group (4 consecutive q)
    const int swz = kq & 15;

    for (int kt = 0; kt < SEQ / KT; kt++) {
        __syncthreads();   // Qs ready (iter 0) / Ks consumers done (iter >0)
#pragma unroll
        for (int i = 0; i < 16; i++) {
            int fidx = i * 256 + tid;          // 0..4095
            int row  = fidx >> 4;              // 0..255
            int d4   = fidx & 15;
            float4 v = *(const float4*)(Kbase + (size_t)(kt * KT + row) * DMODEL + d4 * 4);
            *(float4*)(Ks + row * 64 + ((d4 ^ ((row >> 2) & 15)) << 2)) = v;
        }
        __syncthreads();

        ull acc2[4][4];
#pragma unroll
        for (int j = 0; j < 4; j++)
#pragma unroll
            for (int i = 0; i < 4; i++) acc2[j][i] = 0ull;

#pragma unroll
        for (int d4 = 0; d4 < 16; d4++) {
            f4u kv[4];
#pragma unroll
            for (int i = 0; i < 4; i++)
                kv[i].f = *(float4*)(Ks + (kq * 4 + i) * 64 + ((d4 ^ swz) << 2));
#pragma unroll
            for (int j = 0; j < 4; j++) {
                f4u qv;
                qv.f = *(float4*)(Qs + (qg * 4 + j) * 64 + (d4 << 2));
#pragma unroll
                for (int i = 0; i < 4; i++) {
                    ffma2(acc2[j][i], qv.u[0], kv[i].u[0]);
                    ffma2(acc2[j][i], qv.u[1], kv[i].u[1]);
                }
            }
        }
#pragma unroll
        for (int j = 0; j < 4; j++) {
            float2 r0 = up2(acc2[j][0]), r1 = up2(acc2[j][1]);
            float2 r2 = up2(acc2[j][2]), r3 = up2(acc2[j][3]);
            float4 o = make_float4((r0.x + r0.y) * 0.125f, (r1.x + r1.y) * 0.125f,
                                   (r2.x + r2.y) * 0.125f, (r3.x + r3.y) * 0.125f);
            *(float4*)(S + (size_t)(qg * 4 + j) * SEQ + kt * KT + kq * 4) = o;
        }
    }
    __syncthreads();

    // ---- phase 2: per-row top-U select + softmax + sparse AV ----
    const int lane = tid & 31, wid = tid >> 5;
    unsigned* myhist = hist + wid * 256;

    for (int rr = 0; rr < 2; rr++) {
        const int q = wid * 2 + rr;
        const float* Srow = S + (size_t)q * SEQ;

        // row max
        float m = -1e30f;
        for (int i = lane; i < SEQ; i += 32) m = fmaxf(m, Srow[i]);
#pragma unroll
        for (int off = 16; off; off >>= 1)
            m = fmaxf(m, __shfl_xor_sync(0xffffffffu, m, off));

        // exact radix select of the U_TOP-th largest key (MSB -> LSB, 8b digits)
        unsigned prefix = 0;
        int remaining = U_TOP;
        for (int pass = 0; pass < 4; pass++) {
            const int shift = 24 - pass * 8;
#pragma unroll
            for (int j = 0; j < 8; j++) myhist[lane * 8 + j] = 0;
            __syncwarp();
            for (int i = lane; i < SEQ; i += 32) {
                unsigned key = fkey(Srow[i]);
                bool ok = (pass == 0) || ((key >> (shift + 8)) == prefix);
                if (ok) atomicAdd(&myhist[(key >> shift) & 255], 1u);
            }
            __syncwarp();
            unsigned psum = 0;
#pragma unroll
            for (int j = 0; j < 8; j++) psum += myhist[lane * 8 + j];
            unsigned c = psum;                         // inclusive suffix sum
#pragma unroll
            for (int off = 1; off < 32; off <<= 1) {
                unsigned o = __shfl_down_sync(0xffffffffu, c, off);
                if (lane + off < 32) c += o;
            }
            unsigned mk = __ballot_sync(0xffffffffu, c >= (unsigned)remaining);
            int lsel = 31 - __clz(mk);                 // highest lane crossing
            int digit = 0, newrem = remaining;
            if (lane == lsel) {
                unsigned cum = c - psum;               // count strictly above my bins
                for (int j = 7; j >= 0; j--) {
                    unsigned hv = myhist[lsel * 8 + j];
                    cum += hv;
                    if (cum >= (unsigned)remaining) {
                        digit = lsel * 8 + j;
                        newrem = remaining - (int)(cum - hv);
                        break;
                    }
                }
            }
            digit  = __shfl_sync(0xffffffffu, digit, lsel);
            newrem = __shfl_sync(0xffffffffu, newrem, lsel);
            prefix = (prefix << 8) | (unsigned)digit;
            remaining = newrem;
            __syncwarp();
        }
        const unsigned kth = prefix;  // exact bit pattern of the U-th largest

        // deterministic warp compaction + exp-sum (keep s >= thresh)
        float lsum = 0.f;
        int cnt = 0;
        for (int base = 0; base < SEQ; base += 32) {
            int i = base + lane;
            float s = Srow[i];
            bool keep = fkey(s) >= kth;
            unsigned bm = __ballot_sync(0xffffffffu, keep);
            if (keep) {
                int pos = cnt + __popc(bm & ((1u << lane) - 1u));
                float w = expf(s - m);
                lsum += w;
                if (pos < CAP) { idxl[q * CAP + pos] = i; wl[q * CAP + pos] = w; }
            }
            cnt += __popc(bm);
        }
#pragma unroll
        for (int off = 16; off; off >>= 1)
            lsum += __shfl_xor_sync(0xffffffffu, lsum, off);
        const float scale = 1.f / lsum;

        // sparse AV gather (lane owns dims lane and lane+32)
        float c0 = 0.f, c1 = 0.f;
        if (cnt <= CAP) {
            for (int j = 0; j < cnt; j++) {
                int kkidx = idxl[q * CAP + j];
                float w = wl[q * CAP + j] * scale;
                const float* vr = Vbase + (size_t)kkidx * DMODEL;
                c0 += w * vr[lane];
                c1 += w * vr[lane + 32];
            }
        } else {  // pathological tie overflow: dense fallback (exact)
            for (int i = 0; i < SEQ; i++) {
                float s = Srow[i];
                if (fkey(s) >= kth) {
                    float w = expf(s - m) * scale;
                    const float* vr = Vbase + (size_t)i * DMODEL;
                    c0 += w * vr[lane];
                    c1 += w * vr[lane + 32];
                }
            }
        }
        float* orow = ctx + ((size_t)b * SEQ + q0 + q) * DMODEL + h * HDIM;
        orow[lane]      = c0;
        orow[lane + 32] = c1;
    }
}

// ---------------- launch ----------------------------------------------------
extern "C" void kernel_launch(void* const* d_in, const int* in_sizes, int n_in,
                              void* d_out, int out_size)
{
    const float* x  = (const float*)d_in[0];
    const float* Wq = (const float*)d_in[1];
    const float* bq = (const float*)d_in[2];
    const float* Wk = (const float*)d_in[3];
    const float* bk = (const float*)d_in[4];
    const float* Wv = (const float*)d_in[5];
    const float* bv = (const float*)d_in[6];
    const float* Wo = (const float*)d_in[7];
    const float* bo = (const float*)d_in[8];
    float* out = (float*)d_out;

    float *Q, *K, *V, *C;
    cudaGetSymbolAddress((void**)&Q, g_Q);
    cudaGetSymbolAddress((void**)&K, g_Kp);
    cudaGetSymbolAddress((void**)&V, g_Vp);
    cudaGetSymbolAddress((void**)&C, g_ctx);

    qkv_gemm<<<dim3(24, ROWS / BM), 256>>>(x, Wq, bq, Q, Wk, bk, K, Wv, bv, V);

    cudaFuncSetAttribute(attn_kernel, cudaFuncAttributeMaxDynamicSharedMemorySize,
                         ATTN_SMEM_BYTES);
    attn_kernel<<<dim3(SEQ / TQ, BH), 256, ATTN_SMEM_BYTES>>>(Q, K, V, C);

    sgemm_nt_bias<<<dim3(DMODEL / BN, ROWS / BM), 256>>>(C, Wo, bo, out, ROWS, DMODEL, DMODEL);
}

// round 3
// speedup vs baseline: 1.2598x; 1.2232x over previous
#include <cuda_runtime.h>
#include <cuda_bf16.h>
#include <math.h>

// Problem constants (fixed by the reference)
#define BATCH   2
#define SEQ     2048
#define DMODEL  1024
#define NHEAD   16
#define HDIM    64
#define BH      (BATCH*NHEAD)      // 32
#define ROWS    (BATCH*SEQ)        // 4096
#define U_TOP   38                 // int(5 * ln(2048)) = 38
#define CCAP    256                // candidate buffer per row

typedef unsigned long long ull;

// ---- packed f32x2 helpers (sm_100+: FFMA2 — 2x fp32 FMA per instruction) ---
__device__ __forceinline__ ull pk2(float x, float y) {
    ull r; asm("mov.b64 %0, {%1, %2};" : "=l"(r) : "f"(x), "f"(y)); return r;
}
__device__ __forceinline__ void ffma2(ull& d, ull a, ull b) {
    asm("fma.rn.f32x2 %0, %1, %2, %0;" : "+l"(d) : "l"(a), "l"(b));
}
__device__ __forceinline__ float2 up2(ull v) {
    float2 f; asm("mov.b64 {%0, %1}, %2;" : "=f"(f.x), "=f"(f.y) : "l"(v)); return f;
}
union f4u { float4 f; ull u[2]; };

// ---------------- scratch (allocation-free rule: __device__ globals) --------
__device__ float g_Q[ROWS * DMODEL];
__device__ float g_Kp[ROWS * DMODEL];
__device__ float g_Vp[ROWS * DMODEL];
__device__ float g_ctx[ROWS * DMODEL];

// ---------------- SGEMM:  C[m][n] = sum_k A[m][k] * B[n][k] + bias[n] -------
#define BM 128
#define BN 128
#define BK 16

__device__ __forceinline__
void gemm_body(const float* __restrict__ A, const float* __restrict__ Bw,
               const float* __restrict__ bias, float* __restrict__ C,
               int m0, int n0, int K, int N)
{
    __shared__ float As[BK][BM];
    __shared__ float Bs[BK][BN];

    const int tid = threadIdx.x;
    const int tx = tid & 15;   // n-dir
    const int ty = tid >> 4;   // m-dir

    ull acc2[8][4];            // 8 m-rows x 4 n-pairs (packed fp32x2)
#pragma unroll
    for (int i = 0; i < 8; i++)
#pragma unroll
        for (int j = 0; j < 4; j++) acc2[i][j] = 0ull;

    for (int k0 = 0; k0 < K; k0 += BK) {
#pragma unroll
        for (int i = 0; i < 2; i++) {
            int fidx = tid + i * 256;       // 0..511
            int row  = fidx >> 2;           // 0..127
            int kq   = fidx & 3;            // 0..3  (4 float4 per row)
            float4 va = *(const float4*)(A  + (size_t)(m0 + row) * K + k0 + kq * 4);
            As[kq*4+0][row] = va.x; As[kq*4+1][row] = va.y;
            As[kq*4+2][row] = va.z; As[kq*4+3][row] = va.w;
            float4 vb = *(const float4*)(Bw + (size_t)(n0 + row) * K + k0 + kq * 4);
            Bs[kq*4+0][row] = vb.x; Bs[kq*4+1][row] = vb.y;
            Bs[kq*4+2][row] = vb.z; Bs[kq*4+3][row] = vb.w;
        }
        __syncthreads();
#pragma unroll
        for (int kk = 0; kk < BK; kk++) {
            float a[8];
            *(float4*)&a[0] = *(float4*)&As[kk][ty * 8];
            *(float4*)&a[4] = *(float4*)&As[kk][ty * 8 + 4];
            f4u b0, b1;
            b0.f = *(float4*)&Bs[kk][tx * 8];
            b1.f = *(float4*)&Bs[kk][tx * 8 + 4];
            ull b2[4] = { b0.u[0], b0.u[1], b1.u[0], b1.u[1] };
#pragma unroll
            for (int i = 0; i < 8; i++) {
                ull ai = pk2(a[i], a[i]);
#pragma unroll
                for (int j = 0; j < 4; j++) ffma2(acc2[i][j], ai, b2[j]);
            }
        }
        __syncthreads();
    }

    float bc[8];
#pragma unroll
    for (int j = 0; j < 8; j++) bc[j] = bias[n0 + tx * 8 + j];

#pragma unroll
    for (int i = 0; i < 8; i++) {
        float* crow = C + (size_t)(m0 + ty * 8 + i) * N + n0 + tx * 8;
        float2 p0 = up2(acc2[i][0]), p1 = up2(acc2[i][1]);
        float2 p2 = up2(acc2[i][2]), p3 = up2(acc2[i][3]);
        float4 o0 = make_float4(p0.x + bc[0], p0.y + bc[1], p1.x + bc[2], p1.y + bc[3]);
        float4 o1 = make_float4(p2.x + bc[4], p2.y + bc[5], p3.x + bc[6], p3.y + bc[7]);
        *(float4*)(crow + 0) = o0;
        *(float4*)(crow + 4) = o1;
    }
}

__global__ __launch_bounds__(256)
void sgemm_nt_bias(const float* __restrict__ A, const float* __restrict__ Bw,
                   const float* __restrict__ bias, float* __restrict__ C,
                   int M, int N, int K)
{
    gemm_body(A, Bw, bias, C, blockIdx.y * BM, blockIdx.x * BN, K, N);
}

// fused Q/K/V projection: 3 GEMMs in one grid (blockIdx.x selects matrix)
__global__ __launch_bounds__(256)
void qkv_gemm(const float* __restrict__ x,
              const float* __restrict__ Wq, const float* __restrict__ bq, float* __restrict__ Q,
              const float* __restrict__ Wk, const float* __restrict__ bk, float* __restrict__ K,
              const float* __restrict__ Wv, const float* __restrict__ bv, float* __restrict__ V)
{
    const int sel  = blockIdx.x >> 3;          // 0..2
    const int nblk = blockIdx.x & 7;
    const float* W = (sel == 0) ? Wq : (sel == 1) ? Wk : Wv;
    const float* b = (sel == 0) ? bq : (sel == 1) ? bk : bv;
    float*       C = (sel == 0) ? Q  : (sel == 1) ? K  : V;
    gemm_body(x, W, b, C, blockIdx.y * BM, nblk * BN, DMODEL, DMODEL);
}

// ---------------- fused ProbSparse attention --------------------------------
#define TQ 16
#define KT 256

__device__ __forceinline__ unsigned fkey(float x) {
    unsigned u = __float_as_uint(x);
    return (u & 0x80000000u) ? ~u : (u | 0x80000000u);   // order-preserving map
}
__device__ __forceinline__ float unfkey(unsigned k) {
    unsigned u = (k & 0x80000000u) ? (k ^ 0x80000000u) : ~k;
    return __uint_as_float(u);
}

// exact radix select of the U_TOP-th largest key (fallback path, atomics)
__device__ unsigned radix_select(const float* __restrict__ Srow,
                                 unsigned* __restrict__ myhist, int lane)
{
    unsigned prefix = 0;
    int remaining = U_TOP;
    for (int pass = 0; pass < 4; pass++) {
        const int shift = 24 - pass * 8;
#pragma unroll
        for (int j = 0; j < 8; j++) myhist[lane * 8 + j] = 0;
        __syncwarp();
        for (int i = lane; i < SEQ; i += 32) {
            unsigned key = fkey(Srow[i]);
            bool ok = (pass == 0) || ((key >> (shift + 8)) == prefix);
            if (ok) atomicAdd(&myhist[(key >> shift) & 255], 1u);
        }
        __syncwarp();
        unsigned psum = 0;
#pragma unroll
        for (int j = 0; j < 8; j++) psum += myhist[lane * 8 + j];
        unsigned c = psum;                         // inclusive suffix sum
#pragma unroll
        for (int off = 1; off < 32; off <<= 1) {
            unsigned o = __shfl_down_sync(0xffffffffu, c, off);
            if (lane + off < 32) c += o;
        }
        unsigned mk = __ballot_sync(0xffffffffu, c >= (unsigned)remaining);
        int lsel = 31 - __clz(mk);                 // highest lane crossing
        int digit = 0, newrem = remaining;
        if (lane == lsel) {
            unsigned cum = c - psum;               // count strictly above my bins
            for (int j = 7; j >= 0; j--) {
                unsigned hv = myhist[lsel * 8 + j];
                cum += hv;
                if (cum >= (unsigned)remaining) {
                    digit = lsel * 8 + j;
                    newrem = remaining - (int)(cum - hv);
                    break;
                }
            }
        }
        digit  = __shfl_sync(0xffffffffu, digit, lsel);
        newrem = __shfl_sync(0xffffffffu, newrem, lsel);
        prefix = (prefix << 8) | (unsigned)digit;
        remaining = newrem;
        __syncwarp();
    }
    return prefix;
}

// smem: S[TQ*SEQ] | Qs[TQ*64] | Ks[KT*64] | hist[8*256] | candk[8*256] | candi[8*256]
#define ATTN_SMEM_BYTES ((TQ*SEQ + TQ*64 + KT*64) * 4 + 8*256*4 * 3)

__global__ __launch_bounds__(256)
void attn_kernel(const float* __restrict__ Q, const float* __restrict__ K,
                 const float* __restrict__ V, float* __restrict__ ctx)
{
    extern __shared__ char smraw[];
    float*    S     = (float*)smraw;                 // TQ * SEQ
    float*    Qs    = S  + TQ * SEQ;                 // TQ * 64
    float*    Ks    = Qs + TQ * 64;                  // KT * 64 (xor-swizzled f4)
    unsigned* hist  = (unsigned*)(Ks + KT * 64);     // 8 warps * 256 bins
    unsigned* candk = hist + 8 * 256;                // 8 warps * 256 keys/weights
    int*      candi = (int*)(candk + 8 * 256);       // 8 warps * 256 indices

    const int tid = threadIdx.x;
    const int qt  = blockIdx.x;          // 0..127
    const int bh  = blockIdx.y;          // 0..31
    const int b   = bh >> 4, h = bh & 15;
    const int q0  = qt * TQ;

    const float* Qbase = Q + ((size_t)b * SEQ + q0) * DMODEL + h * HDIM;
    const float* Kbase = K + ((size_t)b * SEQ) * DMODEL + h * HDIM;
    const float* Vbase = V + ((size_t)b * SEQ) * DMODEL + h * HDIM;

    // load Q tile (16 rows x 64)
    {
        int row = tid >> 4, c4 = tid & 15;
        *(float4*)(Qs + row * 64 + c4 * 4) =
            *(const float4*)(Qbase + (size_t)row * DMODEL + c4 * 4);
    }

    // ---- phase 1: scores (packed f32x2 along head dim) ----
    const int kq = tid & 63;   // k-group (4 consecutive k)
    const int qg = tid >> 6;   // q-group (4 consecutive q)
    const int swz = kq & 15;

    for (int kt = 0; kt < SEQ / KT; kt++) {
        __syncthreads();   // Qs ready (iter 0) / Ks consumers done (iter >0)
#pragma unroll
        for (int i = 0; i < 16; i++) {
            int fidx = i * 256 + tid;          // 0..4095
            int row  = fidx >> 4;              // 0..255
            int d4   = fidx & 15;
            float4 v = *(const float4*)(Kbase + (size_t)(kt * KT + row) * DMODEL + d4 * 4);
            *(float4*)(Ks + row * 64 + ((d4 ^ ((row >> 2) & 15)) << 2)) = v;
        }
        __syncthreads();

        ull acc2[4][4];
#pragma unroll
        for (int j = 0; j < 4; j++)
#pragma unroll
            for (int i = 0; i < 4; i++) acc2[j][i] = 0ull;

#pragma unroll
        for (int d4 = 0; d4 < 16; d4++) {
            f4u kv[4];
#pragma unroll
            for (int i = 0; i < 4; i++)
                kv[i].f = *(float4*)(Ks + (kq * 4 + i) * 64 + ((d4 ^ swz) << 2));
#pragma unroll
            for (int j = 0; j < 4; j++) {
                f4u qv;
                qv.f = *(float4*)(Qs + (qg * 4 + j) * 64 + (d4 << 2));
#pragma unroll
                for (int i = 0; i < 4; i++) {
                    ffma2(acc2[j][i], qv.u[0], kv[i].u[0]);
                    ffma2(acc2[j][i], qv.u[1], kv[i].u[1]);
                }
            }
        }
#pragma unroll
        for (int j = 0; j < 4; j++) {
            float2 r0 = up2(acc2[j][0]), r1 = up2(acc2[j][1]);
            float2 r2 = up2(acc2[j][2]), r3 = up2(acc2[j][3]);
            float4 o = make_float4((r0.x + r0.y) * 0.125f, (r1.x + r1.y) * 0.125f,
                                   (r2.x + r2.y) * 0.125f, (r3.x + r3.y) * 0.125f);
            *(float4*)(S + (size_t)(qg * 4 + j) * SEQ + kt * KT + kq * 4) = o;
        }
    }
    __syncthreads();

    // ---- phase 2: per-row top-U select + softmax + sparse AV (atomic-free) --
    const int lane = tid & 31, wid = tid >> 5;
    const unsigned lmlt = (1u << lane) - 1u;
    unsigned* chk = candk + wid * 256;
    int*      chi = candi + wid * 256;
    unsigned* myhist = hist + wid * 256;

    for (int rr = 0; rr < 2; rr++) {
        const int q = wid * 2 + rr;
        const float* Srow = S + (size_t)q * SEQ;

        // pass 1: per-lane max -> row max m, candidate threshold T = min lane-max
        float lm = -1e30f;
        for (int i = lane; i < SEQ; i += 32) lm = fmaxf(lm, Srow[i]);
        float m = lm, tmin = lm;
#pragma unroll
        for (int off = 16; off; off >>= 1) {
            m    = fmaxf(m,    __shfl_xor_sync(0xffffffffu, m,    off));
            tmin = fminf(tmin, __shfl_xor_sync(0xffffffffu, tmin, off));
        }
        const unsigned Tk = fkey(tmin);

        // pass 2: compact all candidates with key >= Tk (complete set)
        int cnt = 0;
        for (int base = 0; base < SEQ; base += 32) {
            int i = base + lane;
            unsigned key = fkey(Srow[i]);
            bool kp = key >= Tk;
            unsigned bm = __ballot_sync(0xffffffffu, kp);
            if (kp) {
                int pos = cnt + __popc(bm & lmlt);
                if (pos < CCAP) { chk[pos] = key; chi[pos] = i; }
            }
            cnt += __popc(bm);
        }
        __syncwarp();

        const bool okc = (cnt >= U_TOP && cnt <= CCAP);
        unsigned kth;
        if (okc) {
            // exact 38th-largest via binary search on key space over candidates
            unsigned ck[8];
#pragma unroll
            for (int t = 0; t < 8; t++) {
                int p = lane + t * 32;
                ck[t] = (p < cnt) ? chk[p] : 0u;
            }
            unsigned lo = Tk, hi = fkey(m);
            while (lo < hi) {
                unsigned mid = lo + ((hi - lo + 1) >> 1);
                int c = 0;
#pragma unroll
                for (int t = 0; t < 8; t++) c += (ck[t] >= mid) ? 1 : 0;
                c = __reduce_add_sync(0xffffffffu, c);
                if (c >= U_TOP) lo = mid; else hi = mid - 1;
            }
            kth = lo;
        } else {
            kth = radix_select(Srow, myhist, lane);   // rare fallback
        }

        // pass 3: final (idx, weight) list + exp-sum
        float lsum = 0.f;
        int nk = 0;
        if (okc) {
            // in-place compaction over candidates
            for (int base = 0; base < cnt; base += 32) {
                int p = base + lane;
                unsigned key = (p < cnt) ? chk[p] : 0u;
                int idx      = (p < cnt) ? chi[p] : 0;
                __syncwarp();
                bool kp = (p < cnt) && (key >= kth);
                unsigned bm = __ballot_sync(0xffffffffu, kp);
                if (kp) {
                    float w = __expf(unfkey(key) - m);
                    lsum += w;
                    int pos = nk + __popc(bm & lmlt);
                    chi[pos] = idx;
                    chk[pos] = __float_as_uint(w);
                }
                nk += __popc(bm);
            }
        } else {
            for (int base = 0; base < SEQ; base += 32) {
                int i = base + lane;
                float s = Srow[i];
                bool kp = fkey(s) >= kth;
                unsigned bm = __ballot_sync(0xffffffffu, kp);
                if (kp) {
                    float w = __expf(s - m);
                    lsum += w;
                    int pos = nk + __popc(bm & lmlt);
                    if (pos < CCAP) { chi[pos] = i; chk[pos] = __float_as_uint(w); }
                }
                nk += __popc(bm);
            }
        }
        __syncwarp();
#pragma unroll
        for (int off = 16; off; off >>= 1)
            lsum += __shfl_xor_sync(0xffffffffu, lsum, off);
        const float scale = 1.f / lsum;

        // pass 4: sparse AV gather (lane owns dims lane and lane+32)
        float c0 = 0.f, c1 = 0.f;
        if (nk <= CCAP) {
            for (int j = 0; j < nk; j++) {
                int kkidx = chi[j];
                float w = __uint_as_float(chk[j]);
                const float* vr = Vbase + (size_t)kkidx * DMODEL;
                c0 += w * vr[lane];
                c1 += w * vr[lane + 32];
            }
        } else {  // pathological tie overflow: dense fallback (exact)
            for (int i = 0; i < SEQ; i++) {
                float s = Srow[i];
                if (fkey(s) >= kth) {
                    float w = __expf(s - m);
                    const float* vr = Vbase + (size_t)i * DMODEL;
                    c0 += w * vr[lane];
                    c1 += w * vr[lane + 32];
                }
            }
        }
        float* orow = ctx + ((size_t)b * SEQ + q0 + q) * DMODEL + h * HDIM;
        orow[lane]      = c0 * scale;
        orow[lane + 32] = c1 * scale;
        __syncwarp();
    }
}

// ---------------- launch ----------------------------------------------------
extern "C" void kernel_launch(void* const* d_in, const int* in_sizes, int n_in,
                              void* d_out, int out_size)
{
    const float* x  = (const float*)d_in[0];
    const float* Wq = (const float*)d_in[1];
    const float* bq = (const float*)d_in[2];
    const float* Wk = (const float*)d_in[3];
    const float* bk = (const float*)d_in[4];
    const float* Wv = (const float*)d_in[5];
    const float* bv = (const float*)d_in[6];
    const float* Wo = (const float*)d_in[7];
    const float* bo = (const float*)d_in[8];
    float* out = (float*)d_out;

    float *Q, *K, *V, *C;
    cudaGetSymbolAddress((void**)&Q, g_Q);
    cudaGetSymbolAddress((void**)&K, g_Kp);
    cudaGetSymbolAddress((void**)&V, g_Vp);
    cudaGetSymbolAddress((void**)&C, g_ctx);

    qkv_gemm<<<dim3(24, ROWS / BM), 256>>>(x, Wq, bq, Q, Wk, bk, K, Wv, bv, V);

    cudaFuncSetAttribute(attn_kernel, cudaFuncAttributeMaxDynamicSharedMemorySize,
                         ATTN_SMEM_BYTES);
    attn_kernel<<<dim3(SEQ / TQ, BH), 256, ATTN_SMEM_BYTES>>>(Q, K, V, C);

    sgemm_nt_bias<<<dim3(DMODEL / BN, ROWS / BM), 256>>>(C, Wo, bo, out, ROWS, DMODEL, DMODEL);
}

// round 7
// speedup vs baseline: 1.3330x; 1.0581x over previous
#include <cuda_runtime.h>
#include <cuda_bf16.h>
#include <math.h>

#define BATCH   2
#define SEQ     2048
#define DMODEL  1024
#define NHEAD   16
#define HDIM    64
#define BH      (BATCH*NHEAD)      // 32
#define ROWS    (BATCH*SEQ)        // 4096
#define U_TOP   38                 // int(5 * ln(2048)) = 38
#define CCAP    192                // candidate buffer per row

typedef unsigned long long ull;

// ---- packed f32x2 helpers ---------------------------------------------------
__device__ __forceinline__ ull pk2(float x, float y) {
    ull r; asm("mov.b64 %0, {%1, %2};" : "=l"(r) : "f"(x), "f"(y)); return r;
}
__device__ __forceinline__ void ffma2(ull& d, ull a, ull b) {
    asm("fma.rn.f32x2 %0, %1, %2, %0;" : "+l"(d) : "l"(a), "l"(b));
}
__device__ __forceinline__ float2 up2(ull v) {
    float2 f; asm("mov.b64 {%0, %1}, %2;" : "=f"(f.x), "=f"(f.y) : "l"(v)); return f;
}
union f4u { float4 f; ull u[2]; };

// ---------------- scratch ----------------------------------------------------
__device__ __align__(256) float g_Q[ROWS * DMODEL];
__device__ __align__(256) float g_Kp[ROWS * DMODEL];
__device__ __align__(256) float g_Vp[ROWS * DMODEL];
__device__ __align__(256) float g_ctx[ROWS * DMODEL];
__device__ __align__(256) __nv_bfloat16 g_xh[ROWS * DMODEL],  g_xl[ROWS * DMODEL];
__device__ __align__(256) __nv_bfloat16 g_ch[ROWS * DMODEL],  g_cl[ROWS * DMODEL];
__device__ __align__(256) __nv_bfloat16 g_wvh[DMODEL*DMODEL], g_wvl[DMODEL*DMODEL];
__device__ __align__(256) __nv_bfloat16 g_woh[DMODEL*DMODEL], g_wol[DMODEL*DMODEL];

// =================== scalar FFMA2 SGEMM (exact R3 numerics) ==================
#define BM 128
#define BN 128
#define BK 16

__device__ __forceinline__
void gemm_body(const float* __restrict__ A, const float* __restrict__ Bw,
               const float* __restrict__ bias, float* __restrict__ C,
               int m0, int n0, int K, int N)
{
    __shared__ float As[BK][BM];
    __shared__ float Bs[BK][BN];

    const int tid = threadIdx.x;
    const int tx = tid & 15;
    const int ty = tid >> 4;

    ull acc2[8][4];
#pragma unroll
    for (int i = 0; i < 8; i++)
#pragma unroll
        for (int j = 0; j < 4; j++) acc2[i][j] = 0ull;

    for (int k0 = 0; k0 < K; k0 += BK) {
#pragma unroll
        for (int i = 0; i < 2; i++) {
            int fidx = tid + i * 256;
            int row  = fidx >> 2;
            int kq   = fidx & 3;
            float4 va = *(const float4*)(A  + (size_t)(m0 + row) * K + k0 + kq * 4);
            As[kq*4+0][row] = va.x; As[kq*4+1][row] = va.y;
            As[kq*4+2][row] = va.z; As[kq*4+3][row] = va.w;
            float4 vb = *(const float4*)(Bw + (size_t)(n0 + row) * K + k0 + kq * 4);
            Bs[kq*4+0][row] = vb.x; Bs[kq*4+1][row] = vb.y;
            Bs[kq*4+2][row] = vb.z; Bs[kq*4+3][row] = vb.w;
        }
        __syncthreads();
#pragma unroll
        for (int kk = 0; kk < BK; kk++) {
            float a[8];
            *(float4*)&a[0] = *(float4*)&As[kk][ty * 8];
            *(float4*)&a[4] = *(float4*)&As[kk][ty * 8 + 4];
            f4u b0, b1;
            b0.f = *(float4*)&Bs[kk][tx * 8];
            b1.f = *(float4*)&Bs[kk][tx * 8 + 4];
            ull b2[4] = { b0.u[0], b0.u[1], b1.u[0], b1.u[1] };
#pragma unroll
            for (int i = 0; i < 8; i++) {
                ull ai = pk2(a[i], a[i]);
#pragma unroll
                for (int j = 0; j < 4; j++) ffma2(acc2[i][j], ai, b2[j]);
            }
        }
        __syncthreads();
    }

    float bc[8];
#pragma unroll
    for (int j = 0; j < 8; j++) bc[j] = bias[n0 + tx * 8 + j];

#pragma unroll
    for (int i = 0; i < 8; i++) {
        float* crow = C + (size_t)(m0 + ty * 8 + i) * N + n0 + tx * 8;
        float2 p0 = up2(acc2[i][0]), p1 = up2(acc2[i][1]);
        float2 p2 = up2(acc2[i][2]), p3 = up2(acc2[i][3]);
        float4 o0 = make_float4(p0.x + bc[0], p0.y + bc[1], p1.x + bc[2], p1.y + bc[3]);
        float4 o1 = make_float4(p2.x + bc[4], p2.y + bc[5], p3.x + bc[6], p3.y + bc[7]);
        *(float4*)(crow + 0) = o0;
        *(float4*)(crow + 4) = o1;
    }
}

// fused Q/K projection (scalar, precision-critical path)
__global__ __launch_bounds__(256)
void qk_gemm(const float* __restrict__ x,
             const float* __restrict__ Wq, const float* __restrict__ bq, float* __restrict__ Q,
             const float* __restrict__ Wk, const float* __restrict__ bk, float* __restrict__ K)
{
    const int sel  = blockIdx.x >> 3;
    const int nblk = blockIdx.x & 7;
    const float* W = (sel == 0) ? Wq : Wk;
    const float* b = (sel == 0) ? bq : bk;
    float*       C = (sel == 0) ? Q  : K;
    gemm_body(x, W, b, C, blockIdx.y * BM, nblk * BN, DMODEL, DMODEL);
}

// =================== HMMA helpers (precision-insensitive GEMMs) ==============
__device__ __forceinline__ unsigned smem_u32(const void* p) {
    unsigned a;
    asm("{ .reg .u64 t; cvta.to.shared.u64 t, %1; cvt.u32.u64 %0, t; }"
        : "=r"(a) : "l"(p));
    return a;
}
__device__ __forceinline__ void ldsm_x4(unsigned* r, unsigned addr) {
    asm volatile("ldmatrix.sync.aligned.m8n8.x4.shared.b16 {%0,%1,%2,%3}, [%4];"
                 : "=r"(r[0]), "=r"(r[1]), "=r"(r[2]), "=r"(r[3]) : "r"(addr));
}
__device__ __forceinline__ void mma16816(float* c, const unsigned* a, const unsigned* b) {
    asm volatile("mma.sync.aligned.m16n8k16.row.col.f32.bf16.bf16.f32 "
                 "{%0,%1,%2,%3}, {%4,%5,%6,%7}, {%8,%9}, {%0,%1,%2,%3};"
                 : "+f"(c[0]), "+f"(c[1]), "+f"(c[2]), "+f"(c[3])
                 : "r"(a[0]), "r"(a[1]), "r"(a[2]), "r"(a[3]), "r"(b[0]), "r"(b[1]));
}
__device__ __forceinline__ void cp_async16(unsigned dst, const void* src) {
    asm volatile("cp.async.cg.shared.global [%0], [%1], 16;" :: "r"(dst), "l"(src));
}
#define CP_COMMIT() asm volatile("cp.async.commit_group;" ::: "memory")

__global__ __launch_bounds__(256)
void cvt_split(const float* __restrict__ src, __nv_bfloat16* __restrict__ hi,
               __nv_bfloat16* __restrict__ lo, int n4)
{
    int i = blockIdx.x * blockDim.x + threadIdx.x;
    for (; i < n4; i += gridDim.x * blockDim.x) {
        float4 v = *((const float4*)src + i);
        __nv_bfloat16 h0 = __float2bfloat16(v.x), h1 = __float2bfloat16(v.y);
        __nv_bfloat16 h2 = __float2bfloat16(v.z), h3 = __float2bfloat16(v.w);
        __nv_bfloat16 l0 = __float2bfloat16(v.x - __bfloat162float(h0));
        __nv_bfloat16 l1 = __float2bfloat16(v.y - __bfloat162float(h1));
        __nv_bfloat16 l2 = __float2bfloat16(v.z - __bfloat162float(h2));
        __nv_bfloat16 l3 = __float2bfloat16(v.w - __bfloat162float(h3));
        __nv_bfloat162 hh[2] = { {h0, h1}, {h2, h3} };
        __nv_bfloat162 ll[2] = { {l0, l1}, {l2, l3} };
        *((float2*)hi + i) = *(float2*)hh;
        *((float2*)lo + i) = *(float2*)ll;
    }
}

// bf16x3 (hi/lo, 3 terms) HMMA GEMM — used ONLY for V and out-proj
#define NCHUNK (DMODEL / 16)
#define ROWB   48
#define TILEB  (128 * ROWB)
#define STAGEB (4 * TILEB)

__device__ __forceinline__
void tc_gemm_body(const __nv_bfloat16* __restrict__ Ah, const __nv_bfloat16* __restrict__ Al,
                  const __nv_bfloat16* __restrict__ Bh, const __nv_bfloat16* __restrict__ Bl,
                  const float* __restrict__ bias, float* __restrict__ C,
                  int m0, int n0, int ldc)
{
    __shared__ __align__(16) char stage[2 * STAGEB];
    const unsigned sbase = smem_u32(stage);

    const int tid  = threadIdx.x;
    const int lane = tid & 31;
    const int wid  = tid >> 5;
    const int wm   = wid & 3;
    const int wn   = wid >> 2;

    const int lrow  = tid >> 1;
    const int lhalf = tid & 1;
    const __nv_bfloat16* gsrc[4] = {
        Ah + (size_t)(m0 + lrow) * DMODEL + lhalf * 8,
        Al + (size_t)(m0 + lrow) * DMODEL + lhalf * 8,
        Bh + (size_t)(n0 + lrow) * DMODEL + lhalf * 8,
        Bl + (size_t)(n0 + lrow) * DMODEL + lhalf * 8 };
    const unsigned sdst = sbase + lrow * ROWB + lhalf * 16;

    float acc[2][8][4];
#pragma unroll
    for (int i = 0; i < 2; i++)
#pragma unroll
        for (int j = 0; j < 8; j++)
#pragma unroll
            for (int k = 0; k < 4; k++) acc[i][j][k] = 0.f;

#pragma unroll
    for (int t = 0; t < 4; t++)
        cp_async16(sdst + t * TILEB, gsrc[t]);
    CP_COMMIT();

    const int arow = wm * 32 + (lane & 15);
    const unsigned a_off = arow * ROWB + (lane >> 4) * 16;
    const int brow = wn * 64 + ((lane >> 4) << 3) + (lane & 7);
    const unsigned b_off = brow * ROWB + ((lane >> 3) & 1) * 16;

    for (int c = 0; c < NCHUNK; c++) {
        if (c + 1 < NCHUNK) {
            const unsigned sd = sdst + ((c + 1) & 1) * STAGEB;
#pragma unroll
            for (int t = 0; t < 4; t++)
                cp_async16(sd + t * TILEB, gsrc[t] + (size_t)(c + 1) * 16);
            CP_COMMIT();
            asm volatile("cp.async.wait_group 1;" ::: "memory");
        } else {
            asm volatile("cp.async.wait_group 0;" ::: "memory");
        }
        __syncthreads();

        const unsigned sb = sbase + (c & 1) * STAGEB;
        unsigned ah[2][4], al[2][4];
#pragma unroll
        for (int mt = 0; mt < 2; mt++) {
            ldsm_x4(ah[mt], sb + 0 * TILEB + a_off + mt * 16 * ROWB);
            ldsm_x4(al[mt], sb + 1 * TILEB + a_off + mt * 16 * ROWB);
        }
#pragma unroll
        for (int p = 0; p < 4; p++) {
            unsigned bh4[4], bl4[4];
            ldsm_x4(bh4, sb + 2 * TILEB + b_off + p * 16 * ROWB);
            ldsm_x4(bl4, sb + 3 * TILEB + b_off + p * 16 * ROWB);
#pragma unroll
            for (int mt = 0; mt < 2; mt++) {
                mma16816(acc[mt][2*p+0], ah[mt], bh4 + 0);
                mma16816(acc[mt][2*p+0], ah[mt], bl4 + 0);
                mma16816(acc[mt][2*p+0], al[mt], bh4 + 0);
                mma16816(acc[mt][2*p+1], ah[mt], bh4 + 2);
                mma16816(acc[mt][2*p+1], ah[mt], bl4 + 2);
                mma16816(acc[mt][2*p+1], al[mt], bh4 + 2);
            }
        }
        __syncthreads();
    }

    const int g = lane >> 2, qd = lane & 3;
#pragma unroll
    for (int mt = 0; mt < 2; mt++) {
        const int rowg = m0 + wm * 32 + mt * 16 + g;
#pragma unroll
        for (int nt = 0; nt < 8; nt++) {
            const int colg = n0 + wn * 64 + nt * 8 + qd * 2;
            const float b0 = bias[colg], b1 = bias[colg + 1];
            float2 o0 = make_float2(acc[mt][nt][0] + b0, acc[mt][nt][1] + b1);
            float2 o1 = make_float2(acc[mt][nt][2] + b0, acc[mt][nt][3] + b1);
            *(float2*)(C + (size_t)rowg * ldc + colg)       = o0;
            *(float2*)(C + (size_t)(rowg + 8) * ldc + colg) = o1;
        }
    }
}

__global__ __launch_bounds__(256)
void tc_gemm1(const __nv_bfloat16* __restrict__ a0, const __nv_bfloat16* __restrict__ a1,
              const __nv_bfloat16* __restrict__ w0, const __nv_bfloat16* __restrict__ w1,
              const float* __restrict__ b, float* __restrict__ C)
{
    tc_gemm_body(a0, a1, w0, w1, b, C, blockIdx.y * 128, blockIdx.x * 128, DMODEL);
}

// ---------------- fused ProbSparse attention (512 threads, 16 warps) --------
#define TQ 16
#define KT 256
#define ATHREADS 512

__device__ __forceinline__ unsigned fkey(float x) {
    unsigned u = __float_as_uint(x);
    return (u & 0x80000000u) ? ~u : (u | 0x80000000u);
}
__device__ __forceinline__ float unfkey(unsigned k) {
    unsigned u = (k & 0x80000000u) ? (k ^ 0x80000000u) : ~k;
    return __uint_as_float(u);
}

__device__ unsigned radix_select(const float* __restrict__ Srow,
                                 unsigned* __restrict__ myhist, int lane)
{
    unsigned prefix = 0;
    int remaining = U_TOP;
    for (int pass = 0; pass < 4; pass++) {
        const int shift = 24 - pass * 8;
#pragma unroll
        for (int j = 0; j < 8; j++) myhist[lane * 8 + j] = 0;
        __syncwarp();
        for (int i = lane; i < SEQ; i += 32) {
            unsigned key = fkey(Srow[i]);
            bool ok = (pass == 0) || ((key >> (shift + 8)) == prefix);
            if (ok) atomicAdd(&myhist[(key >> shift) & 255], 1u);
        }
        __syncwarp();
        unsigned psum = 0;
#pragma unroll
        for (int j = 0; j < 8; j++) psum += myhist[lane * 8 + j];
        unsigned c = psum;
#pragma unroll
        for (int off = 1; off < 32; off <<= 1) {
            unsigned o = __shfl_down_sync(0xffffffffu, c, off);
            if (lane + off < 32) c += o;
        }
        unsigned mk = __ballot_sync(0xffffffffu, c >= (unsigned)remaining);
        int lsel = 31 - __clz(mk);
        int digit = 0, newrem = remaining;
        if (lane == lsel) {
            unsigned cum = c - psum;
            for (int j = 7; j >= 0; j--) {
                unsigned hv = myhist[lsel * 8 + j];
                cum += hv;
                if (cum >= (unsigned)remaining) {
                    digit = lsel * 8 + j;
                    newrem = remaining - (int)(cum - hv);
                    break;
                }
            }
        }
        digit  = __shfl_sync(0xffffffffu, digit, lsel);
        newrem = __shfl_sync(0xffffffffu, newrem, lsel);
        prefix = (prefix << 8) | (unsigned)digit;
        remaining = newrem;
        __syncwarp();
    }
    return prefix;
}

// smem: S[16*2048] | Qs[16*64] | Ks[256*64] | wbuf[16 warps * 384 u32]
#define ATTN_SMEM_BYTES ((TQ*SEQ + TQ*64 + KT*64) * 4 + 16*384*4)

__global__ __launch_bounds__(ATHREADS)
void attn_kernel(const float* __restrict__ Q, const float* __restrict__ K,
                 const float* __restrict__ V, float* __restrict__ ctx)
{
    extern __shared__ char smraw[];
    float*    S    = (float*)smraw;
    float*    Qs   = S  + TQ * SEQ;
    float*    Ks   = Qs + TQ * 64;
    unsigned* wbuf = (unsigned*)(Ks + KT * 64);   // 16 * 384

    const int tid = threadIdx.x;
    const int qt  = blockIdx.x;
    const int bh  = blockIdx.y;
    const int b   = bh >> 4, h = bh & 15;
    const int q0  = qt * TQ;

    const float* Qbase = Q + ((size_t)b * SEQ + q0) * DMODEL + h * HDIM;
    const float* Kbase = K + ((size_t)b * SEQ) * DMODEL + h * HDIM;
    const float* Vbase = V + ((size_t)b * SEQ) * DMODEL + h * HDIM;

    if (tid < 256) {
        int row = tid >> 4, c4 = tid & 15;
        *(float4*)(Qs + row * 64 + c4 * 4) =
            *(const float4*)(Qbase + (size_t)row * DMODEL + c4 * 4);
    }

    // ---- phase 1: scores (FFMA2, 2 q-rows x 4 k-cols per thread) ----
    const int kq = tid & 63;      // k-group (4 consecutive k)
    const int qg = tid >> 6;      // q-group (2 consecutive q), 0..7
    const int swz = kq & 15;

    for (int kt = 0; kt < SEQ / KT; kt++) {
        __syncthreads();
#pragma unroll
        for (int i = 0; i < 8; i++) {
            int fidx = i * ATHREADS + tid;     // 0..4095
            int row  = fidx >> 4;
            int d4   = fidx & 15;
            float4 v = *(const float4*)(Kbase + (size_t)(kt * KT + row) * DMODEL + d4 * 4);
            *(float4*)(Ks + row * 64 + ((d4 ^ ((row >> 2) & 15)) << 2)) = v;
        }
        __syncthreads();

        ull acc2[2][4];
#pragma unroll
        for (int j = 0; j < 2; j++)
#pragma unroll
            for (int i = 0; i < 4; i++) acc2[j][i] = 0ull;

#pragma unroll
        for (int d4 = 0; d4 < 16; d4++) {
            f4u kv[4];
#pragma unroll
            for (int i = 0; i < 4; i++)
                kv[i].f = *(float4*)(Ks + (kq * 4 + i) * 64 + ((d4 ^ swz) << 2));
#pragma unroll
            for (int j = 0; j < 2; j++) {
                f4u qv;
                qv.f = *(float4*)(Qs + (qg * 2 + j) * 64 + (d4 << 2));
#pragma unroll
                for (int i = 0; i < 4; i++) {
                    ffma2(acc2[j][i], qv.u[0], kv[i].u[0]);
                    ffma2(acc2[j][i], qv.u[1], kv[i].u[1]);
                }
            }
        }
#pragma unroll
        for (int j = 0; j < 2; j++) {
            float2 r0 = up2(acc2[j][0]), r1 = up2(acc2[j][1]);
            float2 r2 = up2(acc2[j][2]), r3 = up2(acc2[j][3]);
            float4 o = make_float4((r0.x + r0.y) * 0.125f, (r1.x + r1.y) * 0.125f,
                                   (r2.x + r2.y) * 0.125f, (r3.x + r3.y) * 0.125f);
            *(float4*)(S + (size_t)(qg * 2 + j) * SEQ + kt * KT + kq * 4) = o;
        }
    }
    __syncthreads();

    // ---- phase 2: 1 row per warp ----
    const int lane = tid & 31, wid = tid >> 5;
    const unsigned lmlt = (1u << lane) - 1u;
    unsigned* chk = wbuf + wid * 384;          // CCAP keys / weights
    int*      chi = (int*)(chk + CCAP);        // CCAP indices
    unsigned* myhist = chk;                    // fallback reuses the row (256 u32)

    {
        const int q = wid;
        const float* Srow = S + (size_t)q * SEQ;

        float lm = -1e30f;
        for (int i = lane; i < SEQ; i += 32) lm = fmaxf(lm, Srow[i]);
        float m = lm, tmin = lm;
#pragma unroll
        for (int off = 16; off; off >>= 1) {
            m    = fmaxf(m,    __shfl_xor_sync(0xffffffffu, m,    off));
            tmin = fminf(tmin, __shfl_xor_sync(0xffffffffu, tmin, off));
        }
        const unsigned Tk = fkey(tmin);

        int cnt = 0;
        for (int base = 0; base < SEQ; base += 32) {
            int i = base + lane;
            unsigned key = fkey(Srow[i]);
            bool kp = key >= Tk;
            unsigned bm = __ballot_sync(0xffffffffu, kp);
            if (kp) {
                int pos = cnt + __popc(bm & lmlt);
                if (pos < CCAP) { chk[pos] = key; chi[pos] = i; }
            }
            cnt += __popc(bm);
        }
        __syncwarp();

        const bool okc = (cnt >= U_TOP && cnt <= CCAP);
        unsigned kth;
        if (okc) {
            unsigned ck[6];
#pragma unroll
            for (int t = 0; t < 6; t++) {
                int p = lane + t * 32;
                ck[t] = (p < cnt) ? chk[p] : 0u;
            }
            unsigned lo = Tk, hi = fkey(m);
            while (lo < hi) {
                unsigned mid = lo + ((hi - lo + 1) >> 1);
                int c = 0;
#pragma unroll
                for (int t = 0; t < 6; t++) c += (ck[t] >= mid) ? 1 : 0;
                c = __reduce_add_sync(0xffffffffu, c);
                if (c >= U_TOP) lo = mid; else hi = mid - 1;
            }
            kth = lo;
        } else {
            kth = radix_select(Srow, myhist, lane);
        }

        float lsum = 0.f;
        int nk = 0;
        if (okc) {
            for (int base = 0; base < cnt; base += 32) {
                int p = base + lane;
                unsigned key = (p < cnt) ? chk[p] : 0u;
                int idx      = (p < cnt) ? chi[p] : 0;
                __syncwarp();
                bool kp = (p < cnt) && (key >= kth);
                unsigned bm = __ballot_sync(0xffffffffu, kp);
                if (kp) {
                    float w = __expf(unfkey(key) - m);
                    lsum += w;
                    int pos = nk + __popc(bm & lmlt);
                    chi[pos] = idx;
                    chk[pos] = __float_as_uint(w);
                }
                nk += __popc(bm);
            }
        } else {
            for (int base = 0; base < SEQ; base += 32) {
                int i = base + lane;
                float s = Srow[i];
                bool kp = fkey(s) >= kth;
                unsigned bm = __ballot_sync(0xffffffffu, kp);
                if (kp) {
                    float w = __expf(s - m);
                    lsum += w;
                    int pos = nk + __popc(bm & lmlt);
                    if (pos < CCAP) { chi[pos] = i; chk[pos] = __float_as_uint(w); }
                }
                nk += __popc(bm);
            }
        }
        __syncwarp();
#pragma unroll
        for (int off = 16; off; off >>= 1)
            lsum += __shfl_xor_sync(0xffffffffu, lsum, off);
        const float scale = 1.f / lsum;

        float c0 = 0.f, c1 = 0.f;
        if (nk <= CCAP) {
            for (int j = 0; j < nk; j++) {
                int kkidx = chi[j];
                float w = __uint_as_float(chk[j]);
                const float* vr = Vbase + (size_t)kkidx * DMODEL;
                c0 += w * vr[lane];
                c1 += w * vr[lane + 32];
            }
        } else {
            for (int i = 0; i < SEQ; i++) {
                float s = Srow[i];
                if (fkey(s) >= kth) {
                    float w = __expf(s - m);
                    const float* vr = Vbase + (size_t)i * DMODEL;
                    c0 += w * vr[lane];
                    c1 += w * vr[lane + 32];
                }
            }
        }
        float* orow = ctx + ((size_t)b * SEQ + q0 + q) * DMODEL + h * HDIM;
        orow[lane]      = c0 * scale;
        orow[lane + 32] = c1 * scale;
    }
}

// ---------------- launch ----------------------------------------------------
extern "C" void kernel_launch(void* const* d_in, const int* in_sizes, int n_in,
                              void* d_out, int out_size)
{
    const float* x  = (const float*)d_in[0];
    const float* Wq = (const float*)d_in[1];
    const float* bq = (const float*)d_in[2];
    const float* Wk = (const float*)d_in[3];
    const float* bk = (const float*)d_in[4];
    const float* Wv = (const float*)d_in[5];
    const float* bv = (const float*)d_in[6];
    const float* Wo = (const float*)d_in[7];
    const float* bo = (const float*)d_in[8];
    float* out = (float*)d_out;

    float *Q, *K, *V, *C;
    cudaGetSymbolAddress((void**)&Q, g_Q);
    cudaGetSymbolAddress((void**)&K, g_Kp);
    cudaGetSymbolAddress((void**)&V, g_Vp);
    cudaGetSymbolAddress((void**)&C, g_ctx);
    __nv_bfloat16 *xh,*xl,*ch,*cl,*wvh,*wvl,*woh,*wol;
    cudaGetSymbolAddress((void**)&xh, g_xh);   cudaGetSymbolAddress((void**)&xl, g_xl);
    cudaGetSymbolAddress((void**)&ch, g_ch);   cudaGetSymbolAddress((void**)&cl, g_cl);
    cudaGetSymbolAddress((void**)&wvh, g_wvh); cudaGetSymbolAddress((void**)&wvl, g_wvl);
    cudaGetSymbolAddress((void**)&woh, g_woh); cudaGetSymbolAddress((void**)&wol, g_wol);

    // Q,K: exact fp32 FFMA2 path (selection-critical)
    qk_gemm<<<dim3(16, ROWS / BM), 256>>>(x, Wq, bq, Q, Wk, bk, K);

    // V: HMMA bf16x3 path (precision-insensitive)
    cvt_split<<<1024, 256>>>(x,  xh,  xl,  ROWS*DMODEL/4);
    cvt_split<<<512, 256>>>(Wv, wvh, wvl, DMODEL*DMODEL/4);
    cvt_split<<<512, 256>>>(Wo, woh, wol, DMODEL*DMODEL/4);
    tc_gemm1<<<dim3(DMODEL/128, ROWS/128), 256>>>(xh, xl, wvh, wvl, bv, V);

    cudaFuncSetAttribute(attn_kernel, cudaFuncAttributeMaxDynamicSharedMemorySize,
                         ATTN_SMEM_BYTES);
    attn_kernel<<<dim3(SEQ / TQ, BH), ATHREADS, ATTN_SMEM_BYTES>>>(Q, K, V, C);

    cvt_split<<<1024, 256>>>(C, ch, cl, ROWS*DMODEL/4);
    tc_gemm1<<<dim3(DMODEL/128, ROWS/128), 256>>>(ch, cl, woh, wol, bo, out);
}

// round 8
// speedup vs baseline: 1.4934x; 1.1203x over previous
#include <cuda_runtime.h>
#include <cuda_bf16.h>
#include <math.h>

#define BATCH   2
#define SEQ     2048
#define DMODEL  1024
#define NHEAD   16
#define HDIM    64
#define BH      (BATCH*NHEAD)      // 32
#define ROWS    (BATCH*SEQ)        // 4096
#define U_TOP   38                 // int(5 * ln(2048)) = 38
#define CCAP    192                // candidate buffer per row

typedef unsigned long long ull;

// ---- packed f32x2 helpers ---------------------------------------------------
__device__ __forceinline__ ull pk2(float x, float y) {
    ull r; asm("mov.b64 %0, {%1, %2};" : "=l"(r) : "f"(x), "f"(y)); return r;
}
__device__ __forceinline__ void ffma2(ull& d, ull a, ull b) {
    asm("fma.rn.f32x2 %0, %1, %2, %0;" : "+l"(d) : "l"(a), "l"(b));
}
__device__ __forceinline__ float2 up2(ull v) {
    float2 f; asm("mov.b64 {%0, %1}, %2;" : "=f"(f.x), "=f"(f.y) : "l"(v)); return f;
}
union f4u { float4 f; ull u[2]; };

// ---------------- scratch ----------------------------------------------------
__device__ __align__(256) float g_Q[ROWS * DMODEL];
__device__ __align__(256) float g_Kp[ROWS * DMODEL];
__device__ __align__(256) float g_Vp[ROWS * DMODEL];
__device__ __align__(256) float g_ctx[ROWS * DMODEL];
__device__ __align__(256) __nv_bfloat16 g_xh[ROWS * DMODEL],  g_xl[ROWS * DMODEL];
__device__ __align__(256) __nv_bfloat16 g_ch[ROWS * DMODEL],  g_cl[ROWS * DMODEL];
__device__ __align__(256) __nv_bfloat16 g_wvh[DMODEL*DMODEL], g_wvl[DMODEL*DMODEL];
__device__ __align__(256) __nv_bfloat16 g_woh[DMODEL*DMODEL], g_wol[DMODEL*DMODEL];

// =================== scalar FFMA2 SGEMM (exact R3 numerics) ==================
#define BM 128
#define BN 128
#define BK 16

__device__ __forceinline__
void gemm_body(const float* __restrict__ A, const float* __restrict__ Bw,
               const float* __restrict__ bias, float* __restrict__ C,
               int m0, int n0, int K, int N)
{
    __shared__ float As[BK][BM];
    __shared__ float Bs[BK][BN];

    const int tid = threadIdx.x;
    const int tx = tid & 15;
    const int ty = tid >> 4;

    ull acc2[8][4];
#pragma unroll
    for (int i = 0; i < 8; i++)
#pragma unroll
        for (int j = 0; j < 4; j++) acc2[i][j] = 0ull;

    for (int k0 = 0; k0 < K; k0 += BK) {
#pragma unroll
        for (int i = 0; i < 2; i++) {
            int fidx = tid + i * 256;
            int row  = fidx >> 2;
            int kq   = fidx & 3;
            float4 va = *(const float4*)(A  + (size_t)(m0 + row) * K + k0 + kq * 4);
            As[kq*4+0][row] = va.x; As[kq*4+1][row] = va.y;
            As[kq*4+2][row] = va.z; As[kq*4+3][row] = va.w;
            float4 vb = *(const float4*)(Bw + (size_t)(n0 + row) * K + k0 + kq * 4);
            Bs[kq*4+0][row] = vb.x; Bs[kq*4+1][row] = vb.y;
            Bs[kq*4+2][row] = vb.z; Bs[kq*4+3][row] = vb.w;
        }
        __syncthreads();
#pragma unroll
        for (int kk = 0; kk < BK; kk++) {
            float a[8];
            *(float4*)&a[0] = *(float4*)&As[kk][ty * 8];
            *(float4*)&a[4] = *(float4*)&As[kk][ty * 8 + 4];
            f4u b0, b1;
            b0.f = *(float4*)&Bs[kk][tx * 8];
            b1.f = *(float4*)&Bs[kk][tx * 8 + 4];
            ull b2[4] = { b0.u[0], b0.u[1], b1.u[0], b1.u[1] };
#pragma unroll
            for (int i = 0; i < 8; i++) {
                ull ai = pk2(a[i], a[i]);
#pragma unroll
                for (int j = 0; j < 4; j++) ffma2(acc2[i][j], ai, b2[j]);
            }
        }
        __syncthreads();
    }

    float bc[8];
#pragma unroll
    for (int j = 0; j < 8; j++) bc[j] = bias[n0 + tx * 8 + j];

#pragma unroll
    for (int i = 0; i < 8; i++) {
        float* crow = C + (size_t)(m0 + ty * 8 + i) * N + n0 + tx * 8;
        float2 p0 = up2(acc2[i][0]), p1 = up2(acc2[i][1]);
        float2 p2 = up2(acc2[i][2]), p3 = up2(acc2[i][3]);
        float4 o0 = make_float4(p0.x + bc[0], p0.y + bc[1], p1.x + bc[2], p1.y + bc[3]);
        float4 o1 = make_float4(p2.x + bc[4], p2.y + bc[5], p3.x + bc[6], p3.y + bc[7]);
        *(float4*)(crow + 0) = o0;
        *(float4*)(crow + 4) = o1;
    }
}

__global__ __launch_bounds__(256)
void qk_gemm(const float* __restrict__ x,
             const float* __restrict__ Wq, const float* __restrict__ bq, float* __restrict__ Q,
             const float* __restrict__ Wk, const float* __restrict__ bk, float* __restrict__ K)
{
    const int sel  = blockIdx.x >> 3;
    const int nblk = blockIdx.x & 7;
    const float* W = (sel == 0) ? Wq : Wk;
    const float* b = (sel == 0) ? bq : bk;
    float*       C = (sel == 0) ? Q  : K;
    gemm_body(x, W, b, C, blockIdx.y * BM, nblk * BN, DMODEL, DMODEL);
}

// =================== HMMA helpers (precision-insensitive GEMMs) ==============
__device__ __forceinline__ unsigned smem_u32(const void* p) {
    unsigned a;
    asm("{ .reg .u64 t; cvta.to.shared.u64 t, %1; cvt.u32.u64 %0, t; }"
        : "=r"(a) : "l"(p));
    return a;
}
__device__ __forceinline__ void ldsm_x4(unsigned* r, unsigned addr) {
    asm volatile("ldmatrix.sync.aligned.m8n8.x4.shared.b16 {%0,%1,%2,%3}, [%4];"
                 : "=r"(r[0]), "=r"(r[1]), "=r"(r[2]), "=r"(r[3]) : "r"(addr));
}
__device__ __forceinline__ void mma16816(float* c, const unsigned* a, const unsigned* b) {
    asm volatile("mma.sync.aligned.m16n8k16.row.col.f32.bf16.bf16.f32 "
                 "{%0,%1,%2,%3}, {%4,%5,%6,%7}, {%8,%9}, {%0,%1,%2,%3};"
                 : "+f"(c[0]), "+f"(c[1]), "+f"(c[2]), "+f"(c[3])
                 : "r"(a[0]), "r"(a[1]), "r"(a[2]), "r"(a[3]), "r"(b[0]), "r"(b[1]));
}
__device__ __forceinline__ void cp_async16(unsigned dst, const void* src) {
    asm volatile("cp.async.cg.shared.global [%0], [%1], 16;" :: "r"(dst), "l"(src));
}
#define CP_COMMIT() asm volatile("cp.async.commit_group;" ::: "memory")

__global__ __launch_bounds__(256)
void cvt_split(const float* __restrict__ src, __nv_bfloat16* __restrict__ hi,
               __nv_bfloat16* __restrict__ lo, int n4)
{
    int i = blockIdx.x * blockDim.x + threadIdx.x;
    for (; i < n4; i += gridDim.x * blockDim.x) {
        float4 v = *((const float4*)src + i);
        __nv_bfloat16 h0 = __float2bfloat16(v.x), h1 = __float2bfloat16(v.y);
        __nv_bfloat16 h2 = __float2bfloat16(v.z), h3 = __float2bfloat16(v.w);
        __nv_bfloat16 l0 = __float2bfloat16(v.x - __bfloat162float(h0));
        __nv_bfloat16 l1 = __float2bfloat16(v.y - __bfloat162float(h1));
        __nv_bfloat16 l2 = __float2bfloat16(v.z - __bfloat162float(h2));
        __nv_bfloat16 l3 = __float2bfloat16(v.w - __bfloat162float(h3));
        __nv_bfloat162 hh[2] = { {h0, h1}, {h2, h3} };
        __nv_bfloat162 ll[2] = { {l0, l1}, {l2, l3} };
        *((float2*)hi + i) = *(float2*)hh;
        *((float2*)lo + i) = *(float2*)ll;
    }
}

// bf16x3 (hi/lo, 3 terms) HMMA GEMM — used ONLY for V and out-proj
#define NCHUNK (DMODEL / 16)
#define ROWB   48
#define TILEB  (128 * ROWB)
#define STAGEB (4 * TILEB)

__device__ __forceinline__
void tc_gemm_body(const __nv_bfloat16* __restrict__ Ah, const __nv_bfloat16* __restrict__ Al,
                  const __nv_bfloat16* __restrict__ Bh, const __nv_bfloat16* __restrict__ Bl,
                  const float* __restrict__ bias, float* __restrict__ C,
                  int m0, int n0, int ldc)
{
    __shared__ __align__(16) char stage[2 * STAGEB];
    const unsigned sbase = smem_u32(stage);

    const int tid  = threadIdx.x;
    const int lane = tid & 31;
    const int wid  = tid >> 5;
    const int wm   = wid & 3;
    const int wn   = wid >> 2;

    const int lrow  = tid >> 1;
    const int lhalf = tid & 1;
    const __nv_bfloat16* gsrc[4] = {
        Ah + (size_t)(m0 + lrow) * DMODEL + lhalf * 8,
        Al + (size_t)(m0 + lrow) * DMODEL + lhalf * 8,
        Bh + (size_t)(n0 + lrow) * DMODEL + lhalf * 8,
        Bl + (size_t)(n0 + lrow) * DMODEL + lhalf * 8 };
    const unsigned sdst = sbase + lrow * ROWB + lhalf * 16;

    float acc[2][8][4];
#pragma unroll
    for (int i = 0; i < 2; i++)
#pragma unroll
        for (int j = 0; j < 8; j++)
#pragma unroll
            for (int k = 0; k < 4; k++) acc[i][j][k] = 0.f;

#pragma unroll
    for (int t = 0; t < 4; t++)
        cp_async16(sdst + t * TILEB, gsrc[t]);
    CP_COMMIT();

    const int arow = wm * 32 + (lane & 15);
    const unsigned a_off = arow * ROWB + (lane >> 4) * 16;
    const int brow = wn * 64 + ((lane >> 4) << 3) + (lane & 7);
    const unsigned b_off = brow * ROWB + ((lane >> 3) & 1) * 16;

    for (int c = 0; c < NCHUNK; c++) {
        if (c + 1 < NCHUNK) {
            const unsigned sd = sdst + ((c + 1) & 1) * STAGEB;
#pragma unroll
            for (int t = 0; t < 4; t++)
                cp_async16(sd + t * TILEB, gsrc[t] + (size_t)(c + 1) * 16);
            CP_COMMIT();
            asm volatile("cp.async.wait_group 1;" ::: "memory");
        } else {
            asm volatile("cp.async.wait_group 0;" ::: "memory");
        }
        __syncthreads();

        const unsigned sb = sbase + (c & 1) * STAGEB;
        unsigned ah[2][4], al[2][4];
#pragma unroll
        for (int mt = 0; mt < 2; mt++) {
            ldsm_x4(ah[mt], sb + 0 * TILEB + a_off + mt * 16 * ROWB);
            ldsm_x4(al[mt], sb + 1 * TILEB + a_off + mt * 16 * ROWB);
        }
#pragma unroll
        for (int p = 0; p < 4; p++) {
            unsigned bh4[4], bl4[4];
            ldsm_x4(bh4, sb + 2 * TILEB + b_off + p * 16 * ROWB);
            ldsm_x4(bl4, sb + 3 * TILEB + b_off + p * 16 * ROWB);
#pragma unroll
            for (int mt = 0; mt < 2; mt++) {
                mma16816(acc[mt][2*p+0], ah[mt], bh4 + 0);
                mma16816(acc[mt][2*p+0], ah[mt], bl4 + 0);
                mma16816(acc[mt][2*p+0], al[mt], bh4 + 0);
                mma16816(acc[mt][2*p+1], ah[mt], bh4 + 2);
                mma16816(acc[mt][2*p+1], ah[mt], bl4 + 2);
                mma16816(acc[mt][2*p+1], al[mt], bh4 + 2);
            }
        }
        __syncthreads();
    }

    const int g = lane >> 2, qd = lane & 3;
#pragma unroll
    for (int mt = 0; mt < 2; mt++) {
        const int rowg = m0 + wm * 32 + mt * 16 + g;
#pragma unroll
        for (int nt = 0; nt < 8; nt++) {
            const int colg = n0 + wn * 64 + nt * 8 + qd * 2;
            const float b0 = bias[colg], b1 = bias[colg + 1];
            float2 o0 = make_float2(acc[mt][nt][0] + b0, acc[mt][nt][1] + b1);
            float2 o1 = make_float2(acc[mt][nt][2] + b0, acc[mt][nt][3] + b1);
            *(float2*)(C + (size_t)rowg * ldc + colg)       = o0;
            *(float2*)(C + (size_t)(rowg + 8) * ldc + colg) = o1;
        }
    }
}

__global__ __launch_bounds__(256)
void tc_gemm1(const __nv_bfloat16* __restrict__ a0, const __nv_bfloat16* __restrict__ a1,
              const __nv_bfloat16* __restrict__ w0, const __nv_bfloat16* __restrict__ w1,
              const float* __restrict__ b, float* __restrict__ C)
{
    tc_gemm_body(a0, a1, w0, w1, b, C, blockIdx.y * 128, blockIdx.x * 128, DMODEL);
}

// ---------------- fused ProbSparse attention ---------------------------------
// 512 threads. Phase 1: 4q x 4k register tile, KT=512 k-rows per tile,
// head dim split in two 32-wide chunks; next chunk's K prefetched to registers.
#define TQ 16
#define KT 512
#define ATHREADS 512
#define NCC (SEQ / KT * 2)          // 8 chunk-iterations (4 kt x 2 d-chunks)

__device__ __forceinline__ unsigned fkey(float x) {
    unsigned u = __float_as_uint(x);
    return (u & 0x80000000u) ? ~u : (u | 0x80000000u);
}
__device__ __forceinline__ float unfkey(unsigned k) {
    unsigned u = (k & 0x80000000u) ? (k ^ 0x80000000u) : ~k;
    return __uint_as_float(u);
}

__device__ unsigned radix_select(const float* __restrict__ Srow,
                                 unsigned* __restrict__ myhist, int lane)
{
    unsigned prefix = 0;
    int remaining = U_TOP;
    for (int pass = 0; pass < 4; pass++) {
        const int shift = 24 - pass * 8;
#pragma unroll
        for (int j = 0; j < 8; j++) myhist[lane * 8 + j] = 0;
        __syncwarp();
        for (int i = lane; i < SEQ; i += 32) {
            unsigned key = fkey(Srow[i]);
            bool ok = (pass == 0) || ((key >> (shift + 8)) == prefix);
            if (ok) atomicAdd(&myhist[(key >> shift) & 255], 1u);
        }
        __syncwarp();
        unsigned psum = 0;
#pragma unroll
        for (int j = 0; j < 8; j++) psum += myhist[lane * 8 + j];
        unsigned c = psum;
#pragma unroll
        for (int off = 1; off < 32; off <<= 1) {
            unsigned o = __shfl_down_sync(0xffffffffu, c, off);
            if (lane + off < 32) c += o;
        }
        unsigned mk = __ballot_sync(0xffffffffu, c >= (unsigned)remaining);
        int lsel = 31 - __clz(mk);
        int digit = 0, newrem = remaining;
        if (lane == lsel) {
            unsigned cum = c - psum;
            for (int j = 7; j >= 0; j--) {
                unsigned hv = myhist[lsel * 8 + j];
                cum += hv;
                if (cum >= (unsigned)remaining) {
                    digit = lsel * 8 + j;
                    newrem = remaining - (int)(cum - hv);
                    break;
                }
            }
        }
        digit  = __shfl_sync(0xffffffffu, digit, lsel);
        newrem = __shfl_sync(0xffffffffu, newrem, lsel);
        prefix = (prefix << 8) | (unsigned)digit;
        remaining = newrem;
        __syncwarp();
    }
    return prefix;
}

// smem: S[16*2048] | Qs[16*64] | Ks[512*32 swizzled] | wbuf[16 warps * 384 u32]
#define ATTN_SMEM_BYTES ((TQ*SEQ + TQ*64 + KT*32) * 4 + 16*384*4)

__global__ __launch_bounds__(ATHREADS)
void attn_kernel(const float* __restrict__ Q, const float* __restrict__ K,
                 const float* __restrict__ V, float* __restrict__ ctx)
{
    extern __shared__ char smraw[];
    float*    S    = (float*)smraw;
    float*    Qs   = S  + TQ * SEQ;
    float*    Ks   = Qs + TQ * 64;                 // 512 rows x 32 floats, swizzled
    unsigned* wbuf = (unsigned*)(Ks + KT * 32);    // 16 * 384

    const int tid = threadIdx.x;
    const int qt  = blockIdx.x;
    const int bh  = blockIdx.y;
    const int b   = bh >> 4, h = bh & 15;
    const int q0  = qt * TQ;

    const float* Qbase = Q + ((size_t)b * SEQ + q0) * DMODEL + h * HDIM;
    const float* Kbase = K + ((size_t)b * SEQ) * DMODEL + h * HDIM;
    const float* Vbase = V + ((size_t)b * SEQ) * DMODEL + h * HDIM;

    // load Q tile (16 rows x 64)
    if (tid < 256) {
        int row = tid >> 4, c4 = tid & 15;
        *(float4*)(Qs + row * 64 + c4 * 4) =
            *(const float4*)(Qbase + (size_t)row * DMODEL + c4 * 4);
    }

    // ---- phase 1: scores, 4q x 4k per thread ----
    const int kq  = tid & 127;     // k-group (4 consecutive k rows)
    const int qg  = tid >> 7;      // q-group (4 consecutive q rows), 0..3
    const int swz = kq & 7;

    const int prow = tid >> 3;     // prefetch row within tile (0..63 step... fidx based)
    const int pd4  = tid & 7;

    float4 st[8];
    // prefetch chunk 0
#pragma unroll
    for (int i = 0; i < 8; i++) {
        int row = i * 64 + prow;
        st[i] = *(const float4*)(Kbase + (size_t)row * DMODEL + pd4 * 4);
    }

    ull acc2[4][4];

    for (int cc = 0; cc < NCC; cc++) {
        const int ch = cc & 1;          // d-chunk (0: dims 0-31, 1: dims 32-63)
        const int kb = (cc >> 1) * KT;  // k-row base

        __syncthreads();   // Qs ready (cc==0) / previous chunk's consumers done
        // store staged registers into swizzled Ks
#pragma unroll
        for (int i = 0; i < 8; i++) {
            int row = i * 64 + prow;
            *(float4*)(Ks + row * 32 + ((pd4 ^ ((row >> 2) & 7)) << 2)) = st[i];
        }
        // prefetch next chunk
        if (cc + 1 < NCC) {
            const int nch = (cc + 1) & 1;
            const int nkb = ((cc + 1) >> 1) * KT;
#pragma unroll
            for (int i = 0; i < 8; i++) {
                int row = i * 64 + prow;
                st[i] = *(const float4*)(Kbase + (size_t)(nkb + row) * DMODEL
                                         + nch * 32 + pd4 * 4);
            }
        }
        __syncthreads();   // Ks visible

        if (ch == 0) {
#pragma unroll
            for (int j = 0; j < 4; j++)
#pragma unroll
                for (int i = 0; i < 4; i++) acc2[j][i] = 0ull;
        }

#pragma unroll
        for (int d4 = 0; d4 < 8; d4++) {
            f4u kv[4];
#pragma unroll
            for (int i = 0; i < 4; i++)
                kv[i].f = *(float4*)(Ks + (kq * 4 + i) * 32 + ((d4 ^ swz) << 2));
#pragma unroll
            for (int j = 0; j < 4; j++) {
                f4u qv;
                qv.f = *(float4*)(Qs + (qg * 4 + j) * 64 + ch * 32 + (d4 << 2));
#pragma unroll
                for (int i = 0; i < 4; i++) {
                    ffma2(acc2[j][i], qv.u[0], kv[i].u[0]);
                    ffma2(acc2[j][i], qv.u[1], kv[i].u[1]);
                }
            }
        }

        if (ch == 1) {     // both d-chunks done: flush scores
#pragma unroll
            for (int j = 0; j < 4; j++) {
                float2 r0 = up2(acc2[j][0]), r1 = up2(acc2[j][1]);
                float2 r2 = up2(acc2[j][2]), r3 = up2(acc2[j][3]);
                float4 o = make_float4((r0.x + r0.y) * 0.125f, (r1.x + r1.y) * 0.125f,
                                       (r2.x + r2.y) * 0.125f, (r3.x + r3.y) * 0.125f);
                *(float4*)(S + (size_t)(qg * 4 + j) * SEQ + kb + kq * 4) = o;
            }
        }
    }
    __syncthreads();

    // ---- phase 2: 1 row per warp (unchanged) ----
    const int lane = tid & 31, wid = tid >> 5;
    const unsigned lmlt = (1u << lane) - 1u;
    unsigned* chk = wbuf + wid * 384;
    int*      chi = (int*)(chk + CCAP);
    unsigned* myhist = chk;

    {
        const int q = wid;
        const float* Srow = S + (size_t)q * SEQ;

        float lm = -1e30f;
        for (int i = lane; i < SEQ; i += 32) lm = fmaxf(lm, Srow[i]);
        float m = lm, tmin = lm;
#pragma unroll
        for (int off = 16; off; off >>= 1) {
            m    = fmaxf(m,    __shfl_xor_sync(0xffffffffu, m,    off));
            tmin = fminf(tmin, __shfl_xor_sync(0xffffffffu, tmin, off));
        }
        const unsigned Tk = fkey(tmin);

        int cnt = 0;
        for (int base = 0; base < SEQ; base += 32) {
            int i = base + lane;
            unsigned key = fkey(Srow[i]);
            bool kp = key >= Tk;
            unsigned bm = __ballot_sync(0xffffffffu, kp);
            if (kp) {
                int pos = cnt + __popc(bm & lmlt);
                if (pos < CCAP) { chk[pos] = key; chi[pos] = i; }
            }
            cnt += __popc(bm);
        }
        __syncwarp();

        const bool okc = (cnt >= U_TOP && cnt <= CCAP);
        unsigned kth;
        if (okc) {
            unsigned ck[6];
#pragma unroll
            for (int t = 0; t < 6; t++) {
                int p = lane + t * 32;
                ck[t] = (p < cnt) ? chk[p] : 0u;
            }
            unsigned lo = Tk, hi = fkey(m);
            while (lo < hi) {
                unsigned mid = lo + ((hi - lo + 1) >> 1);
                int c = 0;
#pragma unroll
                for (int t = 0; t < 6; t++) c += (ck[t] >= mid) ? 1 : 0;
                c = __reduce_add_sync(0xffffffffu, c);
                if (c >= U_TOP) lo = mid; else hi = mid - 1;
            }
            kth = lo;
        } else {
            kth = radix_select(Srow, myhist, lane);
        }

        float lsum = 0.f;
        int nk = 0;
        if (okc) {
            for (int base = 0; base < cnt; base += 32) {
                int p = base + lane;
                unsigned key = (p < cnt) ? chk[p] : 0u;
                int idx      = (p < cnt) ? chi[p] : 0;
                __syncwarp();
                bool kp = (p < cnt) && (key >= kth);
                unsigned bm = __ballot_sync(0xffffffffu, kp);
                if (kp) {
                    float w = __expf(unfkey(key) - m);
                    lsum += w;
                    int pos = nk + __popc(bm & lmlt);
                    chi[pos] = idx;
                    chk[pos] = __float_as_uint(w);
                }
                nk += __popc(bm);
            }
        } else {
            for (int base = 0; base < SEQ; base += 32) {
                int i = base + lane;
                float s = Srow[i];
                bool kp = fkey(s) >= kth;
                unsigned bm = __ballot_sync(0xffffffffu, kp);
                if (kp) {
                    float w = __expf(s - m);
                    lsum += w;
                    int pos = nk + __popc(bm & lmlt);
                    if (pos < CCAP) { chi[pos] = i; chk[pos] = __float_as_uint(w); }
                }
                nk += __popc(bm);
            }
        }
        __syncwarp();
#pragma unroll
        for (int off = 16; off; off >>= 1)
            lsum += __shfl_xor_sync(0xffffffffu, lsum, off);
        const float scale = 1.f / lsum;

        float c0 = 0.f, c1 = 0.f;
        if (nk <= CCAP) {
            for (int j = 0; j < nk; j++) {
                int kkidx = chi[j];
                float w = __uint_as_float(chk[j]);
                const float* vr = Vbase + (size_t)kkidx * DMODEL;
                c0 += w * vr[lane];
                c1 += w * vr[lane + 32];
            }
        } else {
            for (int i = 0; i < SEQ; i++) {
                float s = Srow[i];
                if (fkey(s) >= kth) {
                    float w = __expf(s - m);
                    const float* vr = Vbase + (size_t)i * DMODEL;
                    c0 += w * vr[lane];
                    c1 += w * vr[lane + 32];
                }
            }
        }
        float* orow = ctx + ((size_t)b * SEQ + q0 + q) * DMODEL + h * HDIM;
        orow[lane]      = c0 * scale;
        orow[lane + 32] = c1 * scale;
    }
}

// ---------------- launch ----------------------------------------------------
extern "C" void kernel_launch(void* const* d_in, const int* in_sizes, int n_in,
                              void* d_out, int out_size)
{
    const float* x  = (const float*)d_in[0];
    const float* Wq = (const float*)d_in[1];
    const float* bq = (const float*)d_in[2];
    const float* Wk = (const float*)d_in[3];
    const float* bk = (const float*)d_in[4];
    const float* Wv = (const float*)d_in[5];
    const float* bv = (const float*)d_in[6];
    const float* Wo = (const float*)d_in[7];
    const float* bo = (const float*)d_in[8];
    float* out = (float*)d_out;

    float *Q, *K, *V, *C;
    cudaGetSymbolAddress((void**)&Q, g_Q);
    cudaGetSymbolAddress((void**)&K, g_Kp);
    cudaGetSymbolAddress((void**)&V, g_Vp);
    cudaGetSymbolAddress((void**)&C, g_ctx);
    __nv_bfloat16 *xh,*xl,*ch,*cl,*wvh,*wvl,*woh,*wol;
    cudaGetSymbolAddress((void**)&xh, g_xh);   cudaGetSymbolAddress((void**)&xl, g_xl);
    cudaGetSymbolAddress((void**)&ch, g_ch);   cudaGetSymbolAddress((void**)&cl, g_cl);
    cudaGetSymbolAddress((void**)&wvh, g_wvh); cudaGetSymbolAddress((void**)&wvl, g_wvl);
    cudaGetSymbolAddress((void**)&woh, g_woh); cudaGetSymbolAddress((void**)&wol, g_wol);

    // Q,K: exact fp32 FFMA2 path (selection-critical)
    qk_gemm<<<dim3(16, ROWS / BM), 256>>>(x, Wq, bq, Q, Wk, bk, K);

    // V: HMMA bf16x3 path (precision-insensitive)
    cvt_split<<<1024, 256>>>(x,  xh,  xl,  ROWS*DMODEL/4);
    cvt_split<<<512, 256>>>(Wv, wvh, wvl, DMODEL*DMODEL/4);
    cvt_split<<<512, 256>>>(Wo, woh, wol, DMODEL*DMODEL/4);
    tc_gemm1<<<dim3(DMODEL/128, ROWS/128), 256>>>(xh, xl, wvh, wvl, bv, V);

    cudaFuncSetAttribute(attn_kernel, cudaFuncAttributeMaxDynamicSharedMemorySize,
                         ATTN_SMEM_BYTES);
    attn_kernel<<<dim3(SEQ / TQ, BH), ATHREADS, ATTN_SMEM_BYTES>>>(Q, K, V, C);

    cvt_split<<<1024, 256>>>(C, ch, cl, ROWS*DMODEL/4);
    tc_gemm1<<<dim3(DMODEL/128, ROWS/128), 256>>>(ch, cl, woh, wol, bo, out);
}